// round 11
// baseline (speedup 1.0000x reference)
#include <cuda_runtime.h>
#include <cuda_bf16.h>
#include <math_constants.h>
#include <cstdint>

#define NN 100000
#define NE 1600000

typedef unsigned long long ull;

// ---------------- device scratch ----------------
__device__ float  g_h[NN * 160];
__device__ float  g_agg[NN * 128];
__device__ float4 g_as4[NN];
__device__ float4 g_ad4[NN];
__device__ int    g_deg[NN];
__device__ int    g_rowptr[NN + 1];
__device__ int    g_pos[NN];
__device__ int    g_srcs[NE];
// bf16 hi/lo masked weights, W^T layout [n][128] per layer, layer stride 22528
__device__ __nv_bfloat16 g_Bh[3 * 22528];
__device__ __nv_bfloat16 g_Bl[3 * 22528];
__device__ float  g_thr;
__device__ float  g_bnsum[256], g_bnsq[256];   // ping-pong: buf0 (L0->L1), buf1 (L1->L2)
__device__ int    g_bsum[98], g_boff[98];

__device__ __forceinline__ float lrelu(float x) { return (x >= 0.f) ? x : 0.2f * x; }

__device__ __forceinline__ uint32_t smem_u32(const void* p) {
    uint32_t a;
    asm("{ .reg .u64 t; cvta.to.shared.u64 t, %1; cvt.u32.u64 %0, t; }" : "=r"(a) : "l"(p));
    return a;
}
__device__ __forceinline__ void ldmx4(uint32_t addr, uint32_t r[4]) {
    asm volatile("ldmatrix.sync.aligned.m8n8.x4.shared.b16 {%0,%1,%2,%3}, [%4];"
        : "=r"(r[0]), "=r"(r[1]), "=r"(r[2]), "=r"(r[3]) : "r"(addr));
}
__device__ __forceinline__ void ldmx2(uint32_t addr, uint32_t r[2]) {
    asm volatile("ldmatrix.sync.aligned.m8n8.x2.shared.b16 {%0,%1}, [%2];"
        : "=r"(r[0]), "=r"(r[1]) : "r"(addr));
}
__device__ __forceinline__ void mma_bf16(float c[4], const uint32_t a[4],
                                         uint32_t b0, uint32_t b1) {
    asm volatile("mma.sync.aligned.m16n8k16.row.col.f32.bf16.bf16.f32 "
        "{%0,%1,%2,%3}, {%4,%5,%6,%7}, {%8,%9}, {%0,%1,%2,%3};"
        : "+f"(c[0]), "+f"(c[1]), "+f"(c[2]), "+f"(c[3])
        : "r"(a[0]), "r"(a[1]), "r"(a[2]), "r"(a[3]), "r"(b0), "r"(b1));
}
__device__ __forceinline__ void bfsplit(float v, __nv_bfloat16& h, __nv_bfloat16& l) {
    h = __float2bfloat16(v);
    l = __float2bfloat16(v - __bfloat162float(h));
}

// ---------------- exact percentile (bitwise radix rank-select) ----------------
__global__ void thr_kernel(const float* __restrict__ s01, const float* __restrict__ s2) {
    extern __shared__ unsigned sm[];
    unsigned* red = sm + 53248;
    int t = threadIdx.x;
    for (int i = t; i < 32768; i += 1024) sm[i] = __float_as_uint(fabsf(s01[i]));
    for (int i = t; i < 20480; i += 1024) sm[32768 + i] = __float_as_uint(fabsf(s2[i]));
    __syncthreads();
    unsigned prefix = 0;
    int k = 26624;
    for (int bit = 30; bit >= 0; --bit) {
        unsigned himask = 0xFFFFFFFEu << bit;
        unsigned bitm = 1u << bit;
        int cnt = 0;
        for (int i = t; i < 53248; i += 1024) {
            unsigned v = sm[i];
            cnt += ((((v ^ prefix) & himask) == 0u) && ((v & bitm) == 0u)) ? 1 : 0;
        }
        #pragma unroll
        for (int o = 16; o; o >>= 1) cnt += __shfl_xor_sync(0xffffffffu, cnt, o);
        if ((t & 31) == 0) red[t >> 5] = (unsigned)cnt;
        __syncthreads();
        int total = 0;
        #pragma unroll
        for (int w = 0; w < 32; w++) total += (int)red[w];
        if (k >= total) { prefix |= bitm; k -= total; }
        __syncthreads();
    }
    if (t == 0) g_thr = __uint_as_float(prefix);
}

// ---------------- masked weights + attention-folded columns (merged) ----------
__global__ void __launch_bounds__(1024) maskwext_kernel(
        const float* __restrict__ w01, const float* __restrict__ s01,
        const float* __restrict__ att01,
        const float* __restrict__ w2, const float* __restrict__ s2,
        const float* __restrict__ att2) {
    float thr = g_thr;
    int b = blockIdx.x, t = threadIdx.x;
    if (b < 52) {
        int i = b * 1024 + t;
        if (i < 53248) {
            int L, k, n;
            float val;
            if (i < 16384) {
                L = 0; k = i >> 7; n = i & 127;
                val = (fabsf(s01[i]) < thr) ? 0.f : w01[i];
            } else if (i < 32768) {
                int j = i - 16384;
                L = 1; k = j >> 7; n = j & 127;
                val = (fabsf(s01[i]) < thr) ? 0.f : w01[i];
            } else {
                int j = i - 32768;
                L = 2; k = j / 160; n = j - k * 160;
                val = (fabsf(s2[j]) < thr) ? 0.f : w2[j];
            }
            __nv_bfloat16 hi, lo;
            bfsplit(val, hi, lo);
            int idx = L * 22528 + n * 128 + k;
            g_Bh[idx] = hi;
            g_Bl[idx] = lo;
        }
    } else {
        int k = t >> 3, slot = t & 7, sd = slot >> 2, h = slot & 3;
        #pragma unroll
        for (int L = 0; L < 2; L++) {
            float acc = 0.f;
            for (int d = 0; d < 32; d++) {
                int idx = L * 16384 + k * 128 + h * 32 + d;
                float w = (fabsf(s01[idx]) < thr) ? 0.f : w01[idx];
                acc = fmaf(w, att01[L * 256 + sd * 128 + h * 32 + d], acc);
            }
            __nv_bfloat16 hi, lo;
            bfsplit(acc, hi, lo);
            int idx2 = L * 22528 + (128 + slot) * 128 + k;
            g_Bh[idx2] = hi; g_Bl[idx2] = lo;
        }
        {
            float acc = 0.f;
            for (int d = 0; d < 40; d++) {
                int idx = k * 160 + h * 40 + d;
                float w = (fabsf(s2[idx]) < thr) ? 0.f : w2[idx];
                acc = fmaf(w, att2[sd * 160 + h * 40 + d], acc);
            }
            __nv_bfloat16 hi, lo;
            bfsplit(acc, hi, lo);
            int idx2 = 2 * 22528 + (160 + slot) * 128 + k;
            g_Bh[idx2] = hi; g_Bl[idx2] = lo;
        }
    }
}

// ---------------- CSR build ----------------
__global__ void hist_kernel(const int* __restrict__ dst) {
    int e = blockIdx.x * blockDim.x + threadIdx.x;
    if (e < NE) atomicAdd(&g_deg[dst[e]], 1);
}
__global__ void scan1_kernel() {
    __shared__ int red[32];
    int t = threadIdx.x, b = blockIdx.x;
    int i = b * 1024 + t;
    int s = (i < NN) ? g_deg[i] : 0;
    #pragma unroll
    for (int o = 16; o; o >>= 1) s += __shfl_xor_sync(0xffffffffu, s, o);
    if ((t & 31) == 0) red[t >> 5] = s;
    __syncthreads();
    if (t < 32) {
        int x = red[t];
        #pragma unroll
        for (int o = 16; o; o >>= 1) x += __shfl_xor_sync(0xffffffffu, x, o);
        if (t == 0) g_bsum[b] = x;
    }
}
__global__ void scan2_kernel() {
    if (threadIdx.x == 0) {
        int run = 0;
        for (int b = 0; b < 98; b++) { g_boff[b] = run; run += g_bsum[b]; }
        g_rowptr[NN] = run;
    }
}
__global__ void scan3_kernel() {
    __shared__ int sm[1024];
    int t = threadIdx.x, b = blockIdx.x;
    int i = b * 1024 + t;
    int v = (i < NN) ? g_deg[i] : 0;
    sm[t] = v;
    __syncthreads();
    for (int off = 1; off < 1024; off <<= 1) {
        int x = (t >= off) ? sm[t - off] : 0;
        __syncthreads();
        sm[t] += x;
        __syncthreads();
    }
    if (i < NN) {
        int excl = sm[t] - v + g_boff[b];
        g_rowptr[i] = excl;
        g_pos[i] = excl;
        g_deg[i] = 0;
    }
}
__global__ void scatter_kernel(const int* __restrict__ src, const int* __restrict__ dst) {
    int e = blockIdx.x * blockDim.x + threadIdx.x;
    if (blockIdx.x == 0 && threadIdx.x < 256) {
        g_bnsum[threadIdx.x] = 0.f;
        g_bnsq[threadIdx.x] = 0.f;
    }
    if (e < NE) {
        int d = dst[e];
        int p = atomicAdd(&g_pos[d], 1);
        g_srcs[p] = src[e];
    }
}

// ---------------- mma.sync bf16 GEMM, K-chunked (2 CTAs/SM), 512 threads ------
template<int NC>
__global__ void __launch_bounds__(512, 2) gemm_kernel(const float* __restrict__ Xopt,
                                                      int widx, int bnbuf,
                                                      const float* __restrict__ gamma,
                                                      const float* __restrict__ beta) {
    constexpr int NCP = NC + 8;
    constexpr int NT = NCP / 8;
    constexpr int NPAIRS = (NT + 1) / 2;
    constexpr int MAXP = (NPAIRS + 1) / 2;
    constexpr int KS = 72;
    extern __shared__ char dsm[];
    float* SC = (float*)dsm;
    float* SH = SC + 128;
    __nv_bfloat16* Ah = (__nv_bfloat16*)(dsm + 1024);
    __nv_bfloat16* Al = Ah + 128 * KS;
    __nv_bfloat16* Bh = Al + 128 * KS;
    __nv_bfloat16* Bl = Bh + NCP * KS;

    const int useBN = (bnbuf >= 0);
    const float* X = Xopt ? Xopt : g_agg;
    const int tid = threadIdx.x;
    const int wid = tid >> 5, lane = tid & 31;
    const int wy = wid & 7;
    const int wn = wid >> 3;
    const int row0 = blockIdx.x * 128;

    if (useBN && tid < 128) {
        float mu = g_bnsum[bnbuf * 128 + tid] * (1.f / NN);
        float var = g_bnsq[bnbuf * 128 + tid] * (1.f / NN) - mu * mu;
        float sc = rsqrtf(var + 1e-5f) * gamma[tid];
        SC[tid] = sc;
        SH[tid] = fmaf(-mu, sc, beta[tid]);
    }
    if (useBN) __syncthreads();

    float c[MAXP][2][4];
    #pragma unroll
    for (int pi = 0; pi < MAXP; pi++)
        #pragma unroll
        for (int u = 0; u < 2; u++)
            #pragma unroll
            for (int q = 0; q < 4; q++) c[pi][u][q] = 0.f;

    const uint32_t au = smem_u32(Ah), alu = smem_u32(Al);
    const uint32_t bu = smem_u32(Bh), blu = smem_u32(Bl);
    const int arow = wy * 16 + (lane & 15);
    const int acol0 = (lane >> 4) * 8;
    const int brow_x4 = (lane & 7) + ((lane >> 4) * 8);
    const int bcolsel = ((lane >> 3) & 1) * 8;

    for (int kc = 0; kc < 2; kc++) {
        {
            const char* sH = (const char*)(g_Bh + widx * 22528) + kc * 128;
            const char* sL = (const char*)(g_Bl + widx * 22528) + kc * 128;
            for (int i = tid; i < NCP * 8; i += 512) {
                int row = i >> 3, seg = i & 7;
                *(float4*)((char*)Bh + row * (KS * 2) + seg * 16) = *(const float4*)(sH + row * 256 + seg * 16);
                *(float4*)((char*)Bl + row * (KS * 2) + seg * 16) = *(const float4*)(sL + row * 256 + seg * 16);
            }
        }
        {
            __nv_bfloat162* A2h = (__nv_bfloat162*)Ah;
            __nv_bfloat162* A2l = (__nv_bfloat162*)Al;
            for (int i = tid; i < 2048; i += 512) {
                int r = i >> 4, c4l = i & 15;
                int c4 = kc * 16 + c4l;
                int gr = row0 + r;
                float4 v = make_float4(0.f, 0.f, 0.f, 0.f);
                if (gr < NN) {
                    v = ((const float4*)X)[gr * 32 + c4];
                    if (useBN) {
                        float4 sc = ((const float4*)SC)[c4];
                        float4 sh = ((const float4*)SH)[c4];
                        v.x = fmaxf(fmaf(v.x, sc.x, sh.x), 0.f);
                        v.y = fmaxf(fmaf(v.y, sc.y, sh.y), 0.f);
                        v.z = fmaxf(fmaf(v.z, sc.z, sh.z), 0.f);
                        v.w = fmaxf(fmaf(v.w, sc.w, sh.w), 0.f);
                    }
                }
                __nv_bfloat16 hx, lx, hy, ly, hz, lz, hw, lw;
                bfsplit(v.x, hx, lx); bfsplit(v.y, hy, ly);
                bfsplit(v.z, hz, lz); bfsplit(v.w, hw, lw);
                int o2 = r * (KS / 2) + c4l * 2;
                __nv_bfloat162 p0, p1, q0, q1;
                p0.x = hx; p0.y = hy; p1.x = hz; p1.y = hw;
                q0.x = lx; q0.y = ly; q1.x = lz; q1.y = lw;
                A2h[o2] = p0; A2h[o2 + 1] = p1;
                A2l[o2] = q0; A2l[o2 + 1] = q1;
            }
        }
        __syncthreads();

        for (int kb = 0; kb < 4; kb++) {
            uint32_t ah[4], al[4];
            uint32_t aoff = (uint32_t)((arow * KS + kb * 16 + acol0) * 2);
            ldmx4(au + aoff, ah);
            ldmx4(alu + aoff, al);
            #pragma unroll
            for (int pi = 0; pi < MAXP; pi++) {
                int p = wn + 2 * pi;
                if (p >= NPAIRS) break;
                if (2 * p + 1 < NT) {
                    uint32_t bh[4], bl[4];
                    uint32_t boff = (uint32_t)(((p * 16 + brow_x4) * KS + kb * 16 + bcolsel) * 2);
                    ldmx4(bu + boff, bh);
                    ldmx4(blu + boff, bl);
                    mma_bf16(c[pi][0], ah, bh[0], bh[1]);
                    mma_bf16(c[pi][0], ah, bl[0], bl[1]);
                    mma_bf16(c[pi][0], al, bh[0], bh[1]);
                    mma_bf16(c[pi][1], ah, bh[2], bh[3]);
                    mma_bf16(c[pi][1], ah, bl[2], bl[3]);
                    mma_bf16(c[pi][1], al, bh[2], bh[3]);
                } else {
                    uint32_t bh[2], bl[2];
                    int brow2 = 2 * p * 8 + (lane & 7);
                    uint32_t boff = (uint32_t)((brow2 * KS + kb * 16 + bcolsel) * 2);
                    ldmx2(bu + boff, bh);
                    ldmx2(blu + boff, bl);
                    mma_bf16(c[pi][0], ah, bh[0], bh[1]);
                    mma_bf16(c[pi][0], ah, bl[0], bl[1]);
                    mma_bf16(c[pi][0], al, bh[0], bh[1]);
                }
            }
        }
        __syncthreads();
    }

    const int g = lane >> 2, tig = lane & 3;
    const int rA = row0 + wy * 16 + g;
    const int rB = rA + 8;
    const bool okA = rA < NN, okB = rB < NN;
    #pragma unroll
    for (int pi = 0; pi < MAXP; pi++) {
        int p = wn + 2 * pi;
        if (p >= NPAIRS) break;
        #pragma unroll
        for (int u = 0; u < 2; u++) {
            int ntI = 2 * p + u;
            if (ntI >= NT) break;
            if (ntI < NT - 1) {
                if (okA) *(float2*)&g_h[rA * NC + ntI * 8 + tig * 2] = make_float2(c[pi][u][0], c[pi][u][1]);
                if (okB) *(float2*)&g_h[rB * NC + ntI * 8 + tig * 2] = make_float2(c[pi][u][2], c[pi][u][3]);
            } else {
                float e0 = c[pi][u][0], e1 = c[pi][u][1], e2 = c[pi][u][2], e3 = c[pi][u][3];
                float o0 = __shfl_xor_sync(0xffffffffu, e0, 1);
                float o1 = __shfl_xor_sync(0xffffffffu, e1, 1);
                float o2 = __shfl_xor_sync(0xffffffffu, e2, 1);
                float o3 = __shfl_xor_sync(0xffffffffu, e3, 1);
                if (tig == 0) {
                    if (okA) g_as4[rA] = make_float4(e0, e1, o0, o1);
                    if (okB) g_as4[rB] = make_float4(e2, e3, o2, o3);
                } else if (tig == 2) {
                    if (okA) g_ad4[rA] = make_float4(e0, e1, o0, o1);
                    if (okB) g_ad4[rB] = make_float4(e2, e3, o2, o3);
                }
            }
        }
    }
}

// ---------------- softmax + aggregation: 2 warps per node ----------------
template<int C>
__device__ __forceinline__ void gather_step(int s, float alpha, float (&acc)[C], int lane) {
    if (C == 4) {
        float4 hv = ((const float4*)g_h)[s * 32 + lane];
        acc[0] = fmaf(hv.x, alpha, acc[0]);
        acc[1] = fmaf(hv.y, alpha, acc[1]);
        acc[2] = fmaf(hv.z, alpha, acc[2]);
        acc[3] = fmaf(hv.w, alpha, acc[3]);
    } else {
        #pragma unroll
        for (int j = 0; j < C; j++)
            acc[j] = fmaf(g_h[s * (32 * C) + lane * C + j], alpha, acc[j]);
    }
}

template<int D, bool MEAN>
__global__ void __launch_bounds__(256) agg_kernel(float* __restrict__ outMean, int bnbuf) {
    constexpr int C = D / 8;
    __shared__ int    ssrc[4][64];
    __shared__ float4 ealpha[4][64];
    __shared__ float4 sm_m[4][2];
    __shared__ float4 sm_d[4][2];
    __shared__ float  paccf[4][32][C];
    __shared__ float4 bnS[4][32];
    __shared__ float4 bnQ[4][32];

    const int w = threadIdx.x >> 5, lane = threadIdx.x & 31;
    const int half = w & 1, slot = w >> 1;
    const int v = blockIdx.x * 4 + slot;          // grid = NN/4 exactly
    const int head = lane >> 3;
    const int start = g_rowptr[v];
    const int deg = g_rowptr[v + 1] - start;
    const float4 ad = g_ad4[v];
    const bool cached = (deg > 0 && deg <= 64);

    float acc[C];
    #pragma unroll
    for (int j = 0; j < C; j++) acc[j] = 0.f;

    // ---- phase 1: partial max ----
    int   sreg = 0;
    float4 ereg;
    bool  have = false;
    float m0 = -CUDART_INF_F, m1 = m0, m2 = m0, m3 = m0;
    if (cached) {
        int i = half * 32 + lane;
        have = (i < deg);
        if (have) {
            sreg = g_srcs[start + i];
            float4 a = g_as4[sreg];
            ereg.x = lrelu(a.x + ad.x); ereg.y = lrelu(a.y + ad.y);
            ereg.z = lrelu(a.z + ad.z); ereg.w = lrelu(a.w + ad.w);
            m0 = ereg.x; m1 = ereg.y; m2 = ereg.z; m3 = ereg.w;
        }
    } else if (deg > 64) {
        for (int i = half * 32 + lane; i < deg; i += 64) {
            int s = g_srcs[start + i];
            float4 a = g_as4[s];
            m0 = fmaxf(m0, lrelu(a.x + ad.x)); m1 = fmaxf(m1, lrelu(a.y + ad.y));
            m2 = fmaxf(m2, lrelu(a.z + ad.z)); m3 = fmaxf(m3, lrelu(a.w + ad.w));
        }
    }
    #pragma unroll
    for (int o = 16; o; o >>= 1) {
        m0 = fmaxf(m0, __shfl_xor_sync(0xffffffffu, m0, o));
        m1 = fmaxf(m1, __shfl_xor_sync(0xffffffffu, m1, o));
        m2 = fmaxf(m2, __shfl_xor_sync(0xffffffffu, m2, o));
        m3 = fmaxf(m3, __shfl_xor_sync(0xffffffffu, m3, o));
    }
    if (lane == 0) sm_m[slot][half] = make_float4(m0, m1, m2, m3);
    __syncthreads();   // sync 1

    float4 Ma = sm_m[slot][0], Mb = sm_m[slot][1];
    const float M0 = fmaxf(Ma.x, Mb.x), M1 = fmaxf(Ma.y, Mb.y);
    const float M2 = fmaxf(Ma.z, Mb.z), M3 = fmaxf(Ma.w, Mb.w);

    // ---- phase 2: partial denominator ----
    float d0 = 0.f, d1 = 0.f, d2 = 0.f, d3 = 0.f;
    float4 xreg = make_float4(0.f, 0.f, 0.f, 0.f);
    if (cached) {
        if (have) {
            xreg.x = __expf(ereg.x - M0); xreg.y = __expf(ereg.y - M1);
            xreg.z = __expf(ereg.z - M2); xreg.w = __expf(ereg.w - M3);
            d0 = xreg.x; d1 = xreg.y; d2 = xreg.z; d3 = xreg.w;
        }
    } else if (deg > 64) {
        for (int i = half * 32 + lane; i < deg; i += 64) {
            int s = g_srcs[start + i];
            float4 a = g_as4[s];
            d0 += __expf(lrelu(a.x + ad.x) - M0);
            d1 += __expf(lrelu(a.y + ad.y) - M1);
            d2 += __expf(lrelu(a.z + ad.z) - M2);
            d3 += __expf(lrelu(a.w + ad.w) - M3);
        }
    }
    #pragma unroll
    for (int o = 16; o; o >>= 1) {
        d0 += __shfl_xor_sync(0xffffffffu, d0, o);
        d1 += __shfl_xor_sync(0xffffffffu, d1, o);
        d2 += __shfl_xor_sync(0xffffffffu, d2, o);
        d3 += __shfl_xor_sync(0xffffffffu, d3, o);
    }
    if (lane == 0) sm_d[slot][half] = make_float4(d0, d1, d2, d3);
    __syncthreads();   // sync 2

    float4 Da = sm_d[slot][0], Db = sm_d[slot][1];
    const float i0 = 1.f / (Da.x + Db.x + 1e-16f);
    const float i1 = 1.f / (Da.y + Db.y + 1e-16f);
    const float i2 = 1.f / (Da.z + Db.z + 1e-16f);
    const float i3 = 1.f / (Da.w + Db.w + 1e-16f);

    // ---- phase 3: stage src + alpha ----
    if (cached && have) {
        int i = half * 32 + lane;
        ssrc[slot][i] = sreg;
        ealpha[slot][i] = make_float4(xreg.x * i0, xreg.y * i1, xreg.z * i2, xreg.w * i3);
    }
    __syncthreads();   // sync 3

    // ---- phase 4: gather (each warp does its half) ----
    if (cached) {
        int tstart = half * 32;
        int tend = min(deg, tstart + 32);
        #pragma unroll 4
        for (int t = tstart; t < tend; t++) {
            int s = ssrc[slot][t];
            float alpha = ((const float*)&ealpha[slot][t])[head];
            gather_step<C>(s, alpha, acc, lane);
        }
    } else if (deg > 64) {
        const float Mh = (head == 0) ? M0 : (head == 1) ? M1 : (head == 2) ? M2 : M3;
        const float ih = (head == 0) ? i0 : (head == 1) ? i1 : (head == 2) ? i2 : i3;
        const float adh = (head == 0) ? ad.x : (head == 1) ? ad.y : (head == 2) ? ad.z : ad.w;
        for (int t = half; t < deg; t += 2) {
            int s = g_srcs[start + t];
            float ash = ((const float*)&g_as4[s])[head];
            float alpha = __expf(lrelu(ash + adh) - Mh) * ih;
            gather_step<C>(s, alpha, acc, lane);
        }
    }

    // ---- phase 5: combine halves ----
    if (half == 1) {
        #pragma unroll
        for (int j = 0; j < C; j++) paccf[slot][lane][j] = acc[j];
    }
    __syncthreads();   // sync 4

    if (MEAN) {
        if (half == 0) {
            #pragma unroll
            for (int j = 0; j < C; j++) {
                float a = acc[j] + paccf[slot][lane][j];
                a += __shfl_xor_sync(0xffffffffu, a, 8);
                a += __shfl_xor_sync(0xffffffffu, a, 16);
                if (lane < 8) outMean[v * D + lane * C + j] = 0.25f * a;
            }
        }
    } else {
        if (half == 0) {
            float4 a4 = make_float4(acc[0] + paccf[slot][lane][0],
                                    acc[1] + paccf[slot][lane][1],
                                    acc[2] + paccf[slot][lane][2],
                                    acc[3] + paccf[slot][lane][3]);
            ((float4*)g_agg)[v * 32 + lane] = a4;
            bnS[slot][lane] = a4;
            bnQ[slot][lane] = make_float4(a4.x * a4.x, a4.y * a4.y, a4.z * a4.z, a4.w * a4.w);
        }
        __syncthreads();   // sync 5
        int t = threadIdx.x;
        if (t < 128) {
            float s = 0.f;
            #pragma unroll
            for (int i = 0; i < 4; i++) s += ((const float*)&bnS[i][t >> 2])[t & 3];
            atomicAdd(&g_bnsum[bnbuf * 128 + t], s);
        } else {
            int cc = t - 128;
            float q = 0.f;
            #pragma unroll
            for (int i = 0; i < 4; i++) q += ((const float*)&bnQ[i][cc >> 2])[cc & 3];
            atomicAdd(&g_bnsq[bnbuf * 128 + cc], q);
        }
    }
}

// ---------------- launch ----------------
extern "C" void kernel_launch(void* const* d_in, const int* in_sizes, int n_in,
                              void* d_out, int out_size) {
    (void)in_sizes; (void)n_in; (void)out_size;
    const float* x     = (const float*)d_in[0];
    const int*   ei    = (const int*)d_in[1];
    const float* w01   = (const float*)d_in[2];
    const float* s01   = (const float*)d_in[3];
    const float* att01 = (const float*)d_in[4];
    const float* w2    = (const float*)d_in[5];
    const float* s2    = (const float*)d_in[6];
    const float* att2  = (const float*)d_in[7];
    const float* gamma = (const float*)d_in[8];
    const float* beta  = (const float*)d_in[9];
    float* out = (float*)d_out;
    const int* srcp = ei;
    const int* dstp = ei + NE;

    const int THR_SMEM  = (53248 + 32) * 4;
    const int G128_SMEM = 1024 + 2 * 128 * 72 * 2 + 2 * 136 * 72 * 2;   // ~75 KB
    const int G160_SMEM = 1024 + 2 * 128 * 72 * 2 + 2 * 168 * 72 * 2;   // ~84 KB
    cudaFuncSetAttribute(thr_kernel, cudaFuncAttributeMaxDynamicSharedMemorySize, THR_SMEM);
    cudaFuncSetAttribute(gemm_kernel<128>, cudaFuncAttributeMaxDynamicSharedMemorySize, G128_SMEM);
    cudaFuncSetAttribute(gemm_kernel<160>, cudaFuncAttributeMaxDynamicSharedMemorySize, G160_SMEM);

    const int GB = (NN + 127) / 128;   // 782
    const int AB = NN / 4;             // 25000 (2 warps per node)

    thr_kernel<<<1, 1024, THR_SMEM>>>(s01, s2);
    maskwext_kernel<<<53, 1024>>>(w01, s01, att01, w2, s2, att2);

    // Fork: CSR build on a side stream, concurrent with gemm L0.
    cudaStream_t side;
    cudaEvent_t evFork, evJoin;
    cudaStreamCreateWithFlags(&side, cudaStreamNonBlocking);
    cudaEventCreateWithFlags(&evFork, cudaEventDisableTiming);
    cudaEventCreateWithFlags(&evJoin, cudaEventDisableTiming);

    cudaEventRecord(evFork, 0);
    cudaStreamWaitEvent(side, evFork, 0);

    hist_kernel<<<(NE + 255) / 256, 256, 0, side>>>(dstp);
    scan1_kernel<<<98, 1024, 0, side>>>();
    scan2_kernel<<<1, 32, 0, side>>>();
    scan3_kernel<<<98, 1024, 0, side>>>();
    scatter_kernel<<<(NE + 255) / 256, 256, 0, side>>>(srcp, dstp);
    cudaEventRecord(evJoin, side);

    gemm_kernel<128><<<GB, 512, G128_SMEM>>>(x, 0, -1, gamma, beta);

    cudaStreamWaitEvent(0, evJoin, 0);

    agg_kernel<32, false><<<AB, 256>>>(nullptr, 0);
    gemm_kernel<128><<<GB, 512, G128_SMEM>>>(nullptr, 1, 0, gamma, beta);
    agg_kernel<32, false><<<AB, 256>>>(nullptr, 1);
    gemm_kernel<160><<<GB, 512, G160_SMEM>>>(nullptr, 2, 1, gamma + 128, beta + 128);
    agg_kernel<40, true><<<AB, 256>>>(out, 0);

    cudaStreamDestroy(side);
    cudaEventDestroy(evFork);
    cudaEventDestroy(evJoin);
}

// round 12
// speedup vs baseline: 1.2718x; 1.2718x over previous
#include <cuda_runtime.h>
#include <cuda_bf16.h>
#include <math_constants.h>
#include <cstdint>

#define NN 100000
#define NE 1600000

typedef unsigned long long ull;

// ---------------- device scratch ----------------
__device__ float  g_h[NN * 160];
__device__ float  g_agg[NN * 128];
__device__ float4 g_as4[NN];
__device__ float4 g_ad4[NN];
__device__ int    g_deg[NN];
__device__ int    g_rowptr[NN + 1];
__device__ int    g_pos[NN];
__device__ int    g_srcs[NE];
// bf16 hi/lo masked weights, W^T layout [n][128] per layer, layer stride 22528
__device__ __nv_bfloat16 g_Bh[3 * 22528];
__device__ __nv_bfloat16 g_Bl[3 * 22528];
__device__ float  g_thr;
__device__ float  g_bnsum[256], g_bnsq[256];   // ping-pong: buf0 (L0->L1), buf1 (L1->L2)
__device__ int    g_bsum[98], g_boff[98];

__device__ __forceinline__ float lrelu(float x) { return (x >= 0.f) ? x : 0.2f * x; }

__device__ __forceinline__ uint32_t smem_u32(const void* p) {
    uint32_t a;
    asm("{ .reg .u64 t; cvta.to.shared.u64 t, %1; cvt.u32.u64 %0, t; }" : "=r"(a) : "l"(p));
    return a;
}
__device__ __forceinline__ void ldmx4(uint32_t addr, uint32_t r[4]) {
    asm volatile("ldmatrix.sync.aligned.m8n8.x4.shared.b16 {%0,%1,%2,%3}, [%4];"
        : "=r"(r[0]), "=r"(r[1]), "=r"(r[2]), "=r"(r[3]) : "r"(addr));
}
__device__ __forceinline__ void ldmx2(uint32_t addr, uint32_t r[2]) {
    asm volatile("ldmatrix.sync.aligned.m8n8.x2.shared.b16 {%0,%1}, [%2];"
        : "=r"(r[0]), "=r"(r[1]) : "r"(addr));
}
__device__ __forceinline__ void mma_bf16(float c[4], const uint32_t a[4],
                                         uint32_t b0, uint32_t b1) {
    asm volatile("mma.sync.aligned.m16n8k16.row.col.f32.bf16.bf16.f32 "
        "{%0,%1,%2,%3}, {%4,%5,%6,%7}, {%8,%9}, {%0,%1,%2,%3};"
        : "+f"(c[0]), "+f"(c[1]), "+f"(c[2]), "+f"(c[3])
        : "r"(a[0]), "r"(a[1]), "r"(a[2]), "r"(a[3]), "r"(b0), "r"(b1));
}
__device__ __forceinline__ void bfsplit(float v, __nv_bfloat16& h, __nv_bfloat16& l) {
    h = __float2bfloat16(v);
    l = __float2bfloat16(v - __bfloat162float(h));
}

// ---------------- exact percentile (bitwise radix rank-select) ----------------
__global__ void thr_kernel(const float* __restrict__ s01, const float* __restrict__ s2) {
    extern __shared__ unsigned sm[];
    unsigned* red = sm + 53248;
    int t = threadIdx.x;
    for (int i = t; i < 32768; i += 1024) sm[i] = __float_as_uint(fabsf(s01[i]));
    for (int i = t; i < 20480; i += 1024) sm[32768 + i] = __float_as_uint(fabsf(s2[i]));
    __syncthreads();
    unsigned prefix = 0;
    int k = 26624;
    for (int bit = 30; bit >= 0; --bit) {
        unsigned himask = 0xFFFFFFFEu << bit;
        unsigned bitm = 1u << bit;
        int cnt = 0;
        for (int i = t; i < 53248; i += 1024) {
            unsigned v = sm[i];
            cnt += ((((v ^ prefix) & himask) == 0u) && ((v & bitm) == 0u)) ? 1 : 0;
        }
        #pragma unroll
        for (int o = 16; o; o >>= 1) cnt += __shfl_xor_sync(0xffffffffu, cnt, o);
        if ((t & 31) == 0) red[t >> 5] = (unsigned)cnt;
        __syncthreads();
        int total = 0;
        #pragma unroll
        for (int w = 0; w < 32; w++) total += (int)red[w];
        if (k >= total) { prefix |= bitm; k -= total; }
        __syncthreads();
    }
    if (t == 0) g_thr = __uint_as_float(prefix);
}

// ---------------- masked weights + attention-folded columns (merged) ----------
__global__ void __launch_bounds__(1024) maskwext_kernel(
        const float* __restrict__ w01, const float* __restrict__ s01,
        const float* __restrict__ att01,
        const float* __restrict__ w2, const float* __restrict__ s2,
        const float* __restrict__ att2) {
    float thr = g_thr;
    int b = blockIdx.x, t = threadIdx.x;
    if (b < 52) {
        int i = b * 1024 + t;
        if (i < 53248) {
            int L, k, n;
            float val;
            if (i < 16384) {
                L = 0; k = i >> 7; n = i & 127;
                val = (fabsf(s01[i]) < thr) ? 0.f : w01[i];
            } else if (i < 32768) {
                int j = i - 16384;
                L = 1; k = j >> 7; n = j & 127;
                val = (fabsf(s01[i]) < thr) ? 0.f : w01[i];
            } else {
                int j = i - 32768;
                L = 2; k = j / 160; n = j - k * 160;
                val = (fabsf(s2[j]) < thr) ? 0.f : w2[j];
            }
            __nv_bfloat16 hi, lo;
            bfsplit(val, hi, lo);
            int idx = L * 22528 + n * 128 + k;
            g_Bh[idx] = hi;
            g_Bl[idx] = lo;
        }
    } else {
        int k = t >> 3, slot = t & 7, sd = slot >> 2, h = slot & 3;
        #pragma unroll
        for (int L = 0; L < 2; L++) {
            float acc = 0.f;
            for (int d = 0; d < 32; d++) {
                int idx = L * 16384 + k * 128 + h * 32 + d;
                float w = (fabsf(s01[idx]) < thr) ? 0.f : w01[idx];
                acc = fmaf(w, att01[L * 256 + sd * 128 + h * 32 + d], acc);
            }
            __nv_bfloat16 hi, lo;
            bfsplit(acc, hi, lo);
            int idx2 = L * 22528 + (128 + slot) * 128 + k;
            g_Bh[idx2] = hi; g_Bl[idx2] = lo;
        }
        {
            float acc = 0.f;
            for (int d = 0; d < 40; d++) {
                int idx = k * 160 + h * 40 + d;
                float w = (fabsf(s2[idx]) < thr) ? 0.f : w2[idx];
                acc = fmaf(w, att2[sd * 160 + h * 40 + d], acc);
            }
            __nv_bfloat16 hi, lo;
            bfsplit(acc, hi, lo);
            int idx2 = 2 * 22528 + (160 + slot) * 128 + k;
            g_Bh[idx2] = hi; g_Bl[idx2] = lo;
        }
    }
}

// ---------------- CSR build ----------------
__global__ void hist_kernel(const int* __restrict__ dst) {
    int e = blockIdx.x * blockDim.x + threadIdx.x;
    if (e < NE) atomicAdd(&g_deg[dst[e]], 1);
}
__global__ void scan1_kernel() {
    __shared__ int red[32];
    int t = threadIdx.x, b = blockIdx.x;
    int i = b * 1024 + t;
    int s = (i < NN) ? g_deg[i] : 0;
    #pragma unroll
    for (int o = 16; o; o >>= 1) s += __shfl_xor_sync(0xffffffffu, s, o);
    if ((t & 31) == 0) red[t >> 5] = s;
    __syncthreads();
    if (t < 32) {
        int x = red[t];
        #pragma unroll
        for (int o = 16; o; o >>= 1) x += __shfl_xor_sync(0xffffffffu, x, o);
        if (t == 0) g_bsum[b] = x;
    }
}
__global__ void scan2_kernel() {
    if (threadIdx.x == 0) {
        int run = 0;
        for (int b = 0; b < 98; b++) { g_boff[b] = run; run += g_bsum[b]; }
        g_rowptr[NN] = run;
    }
}
__global__ void scan3_kernel() {
    __shared__ int sm[1024];
    int t = threadIdx.x, b = blockIdx.x;
    int i = b * 1024 + t;
    int v = (i < NN) ? g_deg[i] : 0;
    sm[t] = v;
    __syncthreads();
    for (int off = 1; off < 1024; off <<= 1) {
        int x = (t >= off) ? sm[t - off] : 0;
        __syncthreads();
        sm[t] += x;
        __syncthreads();
    }
    if (i < NN) {
        int excl = sm[t] - v + g_boff[b];
        g_rowptr[i] = excl;
        g_pos[i] = excl;
        g_deg[i] = 0;
    }
}
__global__ void scatter_kernel(const int* __restrict__ src, const int* __restrict__ dst) {
    int e = blockIdx.x * blockDim.x + threadIdx.x;
    if (blockIdx.x == 0 && threadIdx.x < 256) {
        g_bnsum[threadIdx.x] = 0.f;
        g_bnsq[threadIdx.x] = 0.f;
    }
    if (e < NE) {
        int d = dst[e];
        int p = atomicAdd(&g_pos[d], 1);
        g_srcs[p] = src[e];
    }
}

// ---------------- mma.sync bf16 GEMM, K-chunked (2 CTAs/SM), 512 threads ------
template<int NC>
__global__ void __launch_bounds__(512, 2) gemm_kernel(const float* __restrict__ Xopt,
                                                      int widx, int bnbuf,
                                                      const float* __restrict__ gamma,
                                                      const float* __restrict__ beta) {
    constexpr int NCP = NC + 8;
    constexpr int NT = NCP / 8;
    constexpr int NPAIRS = (NT + 1) / 2;
    constexpr int MAXP = (NPAIRS + 1) / 2;
    constexpr int KS = 72;
    extern __shared__ char dsm[];
    float* SC = (float*)dsm;
    float* SH = SC + 128;
    __nv_bfloat16* Ah = (__nv_bfloat16*)(dsm + 1024);
    __nv_bfloat16* Al = Ah + 128 * KS;
    __nv_bfloat16* Bh = Al + 128 * KS;
    __nv_bfloat16* Bl = Bh + NCP * KS;

    const int useBN = (bnbuf >= 0);
    const float* X = Xopt ? Xopt : g_agg;
    const int tid = threadIdx.x;
    const int wid = tid >> 5, lane = tid & 31;
    const int wy = wid & 7;
    const int wn = wid >> 3;
    const int row0 = blockIdx.x * 128;

    if (useBN && tid < 128) {
        float mu = g_bnsum[bnbuf * 128 + tid] * (1.f / NN);
        float var = g_bnsq[bnbuf * 128 + tid] * (1.f / NN) - mu * mu;
        float sc = rsqrtf(var + 1e-5f) * gamma[tid];
        SC[tid] = sc;
        SH[tid] = fmaf(-mu, sc, beta[tid]);
    }
    if (useBN) __syncthreads();

    float c[MAXP][2][4];
    #pragma unroll
    for (int pi = 0; pi < MAXP; pi++)
        #pragma unroll
        for (int u = 0; u < 2; u++)
            #pragma unroll
            for (int q = 0; q < 4; q++) c[pi][u][q] = 0.f;

    const uint32_t au = smem_u32(Ah), alu = smem_u32(Al);
    const uint32_t bu = smem_u32(Bh), blu = smem_u32(Bl);
    const int arow = wy * 16 + (lane & 15);
    const int acol0 = (lane >> 4) * 8;
    const int brow_x4 = (lane & 7) + ((lane >> 4) * 8);
    const int bcolsel = ((lane >> 3) & 1) * 8;

    for (int kc = 0; kc < 2; kc++) {
        {
            const char* sH = (const char*)(g_Bh + widx * 22528) + kc * 128;
            const char* sL = (const char*)(g_Bl + widx * 22528) + kc * 128;
            for (int i = tid; i < NCP * 8; i += 512) {
                int row = i >> 3, seg = i & 7;
                *(float4*)((char*)Bh + row * (KS * 2) + seg * 16) = *(const float4*)(sH + row * 256 + seg * 16);
                *(float4*)((char*)Bl + row * (KS * 2) + seg * 16) = *(const float4*)(sL + row * 256 + seg * 16);
            }
        }
        {
            __nv_bfloat162* A2h = (__nv_bfloat162*)Ah;
            __nv_bfloat162* A2l = (__nv_bfloat162*)Al;
            for (int i = tid; i < 2048; i += 512) {
                int r = i >> 4, c4l = i & 15;
                int c4 = kc * 16 + c4l;
                int gr = row0 + r;
                float4 v = make_float4(0.f, 0.f, 0.f, 0.f);
                if (gr < NN) {
                    v = ((const float4*)X)[gr * 32 + c4];
                    if (useBN) {
                        float4 sc = ((const float4*)SC)[c4];
                        float4 sh = ((const float4*)SH)[c4];
                        v.x = fmaxf(fmaf(v.x, sc.x, sh.x), 0.f);
                        v.y = fmaxf(fmaf(v.y, sc.y, sh.y), 0.f);
                        v.z = fmaxf(fmaf(v.z, sc.z, sh.z), 0.f);
                        v.w = fmaxf(fmaf(v.w, sc.w, sh.w), 0.f);
                    }
                }
                __nv_bfloat16 hx, lx, hy, ly, hz, lz, hw, lw;
                bfsplit(v.x, hx, lx); bfsplit(v.y, hy, ly);
                bfsplit(v.z, hz, lz); bfsplit(v.w, hw, lw);
                int o2 = r * (KS / 2) + c4l * 2;
                __nv_bfloat162 p0, p1, q0, q1;
                p0.x = hx; p0.y = hy; p1.x = hz; p1.y = hw;
                q0.x = lx; q0.y = ly; q1.x = lz; q1.y = lw;
                A2h[o2] = p0; A2h[o2 + 1] = p1;
                A2l[o2] = q0; A2l[o2 + 1] = q1;
            }
        }
        __syncthreads();

        for (int kb = 0; kb < 4; kb++) {
            uint32_t ah[4], al[4];
            uint32_t aoff = (uint32_t)((arow * KS + kb * 16 + acol0) * 2);
            ldmx4(au + aoff, ah);
            ldmx4(alu + aoff, al);
            #pragma unroll
            for (int pi = 0; pi < MAXP; pi++) {
                int p = wn + 2 * pi;
                if (p >= NPAIRS) break;
                if (2 * p + 1 < NT) {
                    uint32_t bh[4], bl[4];
                    uint32_t boff = (uint32_t)(((p * 16 + brow_x4) * KS + kb * 16 + bcolsel) * 2);
                    ldmx4(bu + boff, bh);
                    ldmx4(blu + boff, bl);
                    mma_bf16(c[pi][0], ah, bh[0], bh[1]);
                    mma_bf16(c[pi][0], ah, bl[0], bl[1]);
                    mma_bf16(c[pi][0], al, bh[0], bh[1]);
                    mma_bf16(c[pi][1], ah, bh[2], bh[3]);
                    mma_bf16(c[pi][1], ah, bl[2], bl[3]);
                    mma_bf16(c[pi][1], al, bh[2], bh[3]);
                } else {
                    uint32_t bh[2], bl[2];
                    int brow2 = 2 * p * 8 + (lane & 7);
                    uint32_t boff = (uint32_t)((brow2 * KS + kb * 16 + bcolsel) * 2);
                    ldmx2(bu + boff, bh);
                    ldmx2(blu + boff, bl);
                    mma_bf16(c[pi][0], ah, bh[0], bh[1]);
                    mma_bf16(c[pi][0], ah, bl[0], bl[1]);
                    mma_bf16(c[pi][0], al, bh[0], bh[1]);
                }
            }
        }
        __syncthreads();
    }

    const int g = lane >> 2, tig = lane & 3;
    const int rA = row0 + wy * 16 + g;
    const int rB = rA + 8;
    const bool okA = rA < NN, okB = rB < NN;
    #pragma unroll
    for (int pi = 0; pi < MAXP; pi++) {
        int p = wn + 2 * pi;
        if (p >= NPAIRS) break;
        #pragma unroll
        for (int u = 0; u < 2; u++) {
            int ntI = 2 * p + u;
            if (ntI >= NT) break;
            if (ntI < NT - 1) {
                if (okA) *(float2*)&g_h[rA * NC + ntI * 8 + tig * 2] = make_float2(c[pi][u][0], c[pi][u][1]);
                if (okB) *(float2*)&g_h[rB * NC + ntI * 8 + tig * 2] = make_float2(c[pi][u][2], c[pi][u][3]);
            } else {
                float e0 = c[pi][u][0], e1 = c[pi][u][1], e2 = c[pi][u][2], e3 = c[pi][u][3];
                float o0 = __shfl_xor_sync(0xffffffffu, e0, 1);
                float o1 = __shfl_xor_sync(0xffffffffu, e1, 1);
                float o2 = __shfl_xor_sync(0xffffffffu, e2, 1);
                float o3 = __shfl_xor_sync(0xffffffffu, e3, 1);
                if (tig == 0) {
                    if (okA) g_as4[rA] = make_float4(e0, e1, o0, o1);
                    if (okB) g_as4[rB] = make_float4(e2, e3, o2, o3);
                } else if (tig == 2) {
                    if (okA) g_ad4[rA] = make_float4(e0, e1, o0, o1);
                    if (okB) g_ad4[rB] = make_float4(e2, e3, o2, o3);
                }
            }
        }
    }
}

// ---------------- softmax + aggregation (single warp/node, dual accumulators) --
template<int C>
__device__ __forceinline__ void gather_step(int s, float alpha, float (&acc)[C], int lane) {
    if (C == 4) {
        float4 hv = ((const float4*)g_h)[s * 32 + lane];
        acc[0] = fmaf(hv.x, alpha, acc[0]);
        acc[1] = fmaf(hv.y, alpha, acc[1]);
        acc[2] = fmaf(hv.z, alpha, acc[2]);
        acc[3] = fmaf(hv.w, alpha, acc[3]);
    } else {
        #pragma unroll
        for (int j = 0; j < C; j++)
            acc[j] = fmaf(g_h[s * (32 * C) + lane * C + j], alpha, acc[j]);
    }
}

template<int D, bool MEAN>
__global__ void __launch_bounds__(256) agg_kernel(float* __restrict__ outMean, int bnbuf) {
    constexpr int C = D / 8;
    __shared__ int    ssrc[8][64];
    __shared__ float4 ealpha[8][64];
    __shared__ float4 bnS[8][32];
    __shared__ float4 bnQ[8][32];
    int w = threadIdx.x >> 5, lane = threadIdx.x & 31;
    int v = blockIdx.x * 8 + w;
    int head = lane >> 3;
    int start = g_rowptr[v];
    int deg = g_rowptr[v + 1] - start;
    float4 ad = g_ad4[v];

    float acc[C], acc2[C];
    #pragma unroll
    for (int j = 0; j < C; j++) { acc[j] = 0.f; acc2[j] = 0.f; }

    if (deg > 0 && deg <= 64) {
        int s0 = 0, s1 = 0;
        float4 e0, e1;
        bool h0 = lane < deg, h1 = lane + 32 < deg;
        float m0 = -CUDART_INF_F, m1 = m0, m2 = m0, m3 = m0;
        if (h0) {
            s0 = g_srcs[start + lane];
            float4 a = g_as4[s0];
            e0.x = lrelu(a.x + ad.x); e0.y = lrelu(a.y + ad.y);
            e0.z = lrelu(a.z + ad.z); e0.w = lrelu(a.w + ad.w);
            m0 = e0.x; m1 = e0.y; m2 = e0.z; m3 = e0.w;
        }
        if (h1) {
            s1 = g_srcs[start + lane + 32];
            float4 a = g_as4[s1];
            e1.x = lrelu(a.x + ad.x); e1.y = lrelu(a.y + ad.y);
            e1.z = lrelu(a.z + ad.z); e1.w = lrelu(a.w + ad.w);
            m0 = fmaxf(m0, e1.x); m1 = fmaxf(m1, e1.y);
            m2 = fmaxf(m2, e1.z); m3 = fmaxf(m3, e1.w);
        }
        #pragma unroll
        for (int o = 16; o; o >>= 1) {
            m0 = fmaxf(m0, __shfl_xor_sync(0xffffffffu, m0, o));
            m1 = fmaxf(m1, __shfl_xor_sync(0xffffffffu, m1, o));
            m2 = fmaxf(m2, __shfl_xor_sync(0xffffffffu, m2, o));
            m3 = fmaxf(m3, __shfl_xor_sync(0xffffffffu, m3, o));
        }
        float d0 = 0.f, d1 = 0.f, d2 = 0.f, d3 = 0.f;
        float x00=0,x01=0,x02=0,x03=0, x10=0,x11=0,x12=0,x13=0;
        if (h0) {
            x00 = __expf(e0.x - m0); x01 = __expf(e0.y - m1);
            x02 = __expf(e0.z - m2); x03 = __expf(e0.w - m3);
            d0 += x00; d1 += x01; d2 += x02; d3 += x03;
        }
        if (h1) {
            x10 = __expf(e1.x - m0); x11 = __expf(e1.y - m1);
            x12 = __expf(e1.z - m2); x13 = __expf(e1.w - m3);
            d0 += x10; d1 += x11; d2 += x12; d3 += x13;
        }
        #pragma unroll
        for (int o = 16; o; o >>= 1) {
            d0 += __shfl_xor_sync(0xffffffffu, d0, o);
            d1 += __shfl_xor_sync(0xffffffffu, d1, o);
            d2 += __shfl_xor_sync(0xffffffffu, d2, o);
            d3 += __shfl_xor_sync(0xffffffffu, d3, o);
        }
        float i0 = 1.f / (d0 + 1e-16f), i1 = 1.f / (d1 + 1e-16f);
        float i2 = 1.f / (d2 + 1e-16f), i3 = 1.f / (d3 + 1e-16f);
        if (h0) {
            ssrc[w][lane] = s0;
            ealpha[w][lane] = make_float4(x00 * i0, x01 * i1, x02 * i2, x03 * i3);
        }
        if (h1) {
            ssrc[w][lane + 32] = s1;
            ealpha[w][lane + 32] = make_float4(x10 * i0, x11 * i1, x12 * i2, x13 * i3);
        }
        __syncwarp();
        // dual-accumulator gather: even edges -> acc, odd edges -> acc2
        int t = 0;
        #pragma unroll 2
        for (; t + 1 < deg; t += 2) {
            int sa = ssrc[w][t];
            int sb = ssrc[w][t + 1];
            float aa = ((const float*)&ealpha[w][t])[head];
            float ab = ((const float*)&ealpha[w][t + 1])[head];
            gather_step<C>(sa, aa, acc, lane);
            gather_step<C>(sb, ab, acc2, lane);
        }
        if (t < deg) {
            int sa = ssrc[w][t];
            float aa = ((const float*)&ealpha[w][t])[head];
            gather_step<C>(sa, aa, acc, lane);
        }
    } else if (deg > 64) {
        float m0 = -CUDART_INF_F, m1 = m0, m2 = m0, m3 = m0;
        for (int i = lane; i < deg; i += 32) {
            int s = g_srcs[start + i];
            float4 a = g_as4[s];
            m0 = fmaxf(m0, lrelu(a.x + ad.x)); m1 = fmaxf(m1, lrelu(a.y + ad.y));
            m2 = fmaxf(m2, lrelu(a.z + ad.z)); m3 = fmaxf(m3, lrelu(a.w + ad.w));
        }
        #pragma unroll
        for (int o = 16; o; o >>= 1) {
            m0 = fmaxf(m0, __shfl_xor_sync(0xffffffffu, m0, o));
            m1 = fmaxf(m1, __shfl_xor_sync(0xffffffffu, m1, o));
            m2 = fmaxf(m2, __shfl_xor_sync(0xffffffffu, m2, o));
            m3 = fmaxf(m3, __shfl_xor_sync(0xffffffffu, m3, o));
        }
        float d0 = 0.f, d1 = 0.f, d2 = 0.f, d3 = 0.f;
        for (int i = lane; i < deg; i += 32) {
            int s = g_srcs[start + i];
            float4 a = g_as4[s];
            d0 += __expf(lrelu(a.x + ad.x) - m0);
            d1 += __expf(lrelu(a.y + ad.y) - m1);
            d2 += __expf(lrelu(a.z + ad.z) - m2);
            d3 += __expf(lrelu(a.w + ad.w) - m3);
        }
        #pragma unroll
        for (int o = 16; o; o >>= 1) {
            d0 += __shfl_xor_sync(0xffffffffu, d0, o);
            d1 += __shfl_xor_sync(0xffffffffu, d1, o);
            d2 += __shfl_xor_sync(0xffffffffu, d2, o);
            d3 += __shfl_xor_sync(0xffffffffu, d3, o);
        }
        float denh = (head == 0) ? d0 : (head == 1) ? d1 : (head == 2) ? d2 : d3;
        float mxh  = (head == 0) ? m0 : (head == 1) ? m1 : (head == 2) ? m2 : m3;
        float adh  = (head == 0) ? ad.x : (head == 1) ? ad.y : (head == 2) ? ad.z : ad.w;
        float invh = 1.f / (denh + 1e-16f);
        for (int t = 0; t < deg; t++) {
            int s = g_srcs[start + t];
            float ash = ((const float*)&g_as4[s])[head];
            float alpha = __expf(lrelu(ash + adh) - mxh) * invh;
            gather_step<C>(s, alpha, acc, lane);
        }
    }

    #pragma unroll
    for (int j = 0; j < C; j++) acc[j] += acc2[j];

    if (MEAN) {
        #pragma unroll
        for (int j = 0; j < C; j++) {
            float a = acc[j];
            a += __shfl_xor_sync(0xffffffffu, a, 8);
            a += __shfl_xor_sync(0xffffffffu, a, 16);
            if (lane < 8) outMean[v * D + lane * C + j] = 0.25f * a;
        }
    } else {
        float4 a4 = make_float4(acc[0], acc[1], acc[2], acc[3]);
        ((float4*)g_agg)[v * 32 + lane] = a4;
        bnS[w][lane] = a4;
        bnQ[w][lane] = make_float4(a4.x * a4.x, a4.y * a4.y, a4.z * a4.z, a4.w * a4.w);
        __syncthreads();
        int t = threadIdx.x;
        if (t < 128) {
            float s = 0.f;
            #pragma unroll
            for (int i = 0; i < 8; i++) s += ((const float*)&bnS[i][t >> 2])[t & 3];
            atomicAdd(&g_bnsum[bnbuf * 128 + t], s);
        } else {
            int cc = t - 128;
            float q = 0.f;
            #pragma unroll
            for (int i = 0; i < 8; i++) q += ((const float*)&bnQ[i][cc >> 2])[cc & 3];
            atomicAdd(&g_bnsq[bnbuf * 128 + cc], q);
        }
    }
}

// ---------------- launch ----------------
extern "C" void kernel_launch(void* const* d_in, const int* in_sizes, int n_in,
                              void* d_out, int out_size) {
    (void)in_sizes; (void)n_in; (void)out_size;
    const float* x     = (const float*)d_in[0];
    const int*   ei    = (const int*)d_in[1];
    const float* w01   = (const float*)d_in[2];
    const float* s01   = (const float*)d_in[3];
    const float* att01 = (const float*)d_in[4];
    const float* w2    = (const float*)d_in[5];
    const float* s2    = (const float*)d_in[6];
    const float* att2  = (const float*)d_in[7];
    const float* gamma = (const float*)d_in[8];
    const float* beta  = (const float*)d_in[9];
    float* out = (float*)d_out;
    const int* srcp = ei;
    const int* dstp = ei + NE;

    const int THR_SMEM  = (53248 + 32) * 4;
    const int G128_SMEM = 1024 + 2 * 128 * 72 * 2 + 2 * 136 * 72 * 2;   // ~75 KB
    const int G160_SMEM = 1024 + 2 * 128 * 72 * 2 + 2 * 168 * 72 * 2;   // ~84 KB
    cudaFuncSetAttribute(thr_kernel, cudaFuncAttributeMaxDynamicSharedMemorySize, THR_SMEM);
    cudaFuncSetAttribute(gemm_kernel<128>, cudaFuncAttributeMaxDynamicSharedMemorySize, G128_SMEM);
    cudaFuncSetAttribute(gemm_kernel<160>, cudaFuncAttributeMaxDynamicSharedMemorySize, G160_SMEM);

    const int GB = (NN + 127) / 128;   // 782
    const int AB = NN / 8;             // 12500 (warp per node)

    thr_kernel<<<1, 1024, THR_SMEM>>>(s01, s2);
    maskwext_kernel<<<53, 1024>>>(w01, s01, att01, w2, s2, att2);

    // Fork: CSR build on a side stream, concurrent with gemm L0.
    cudaStream_t side;
    cudaEvent_t evFork, evJoin;
    cudaStreamCreateWithFlags(&side, cudaStreamNonBlocking);
    cudaEventCreateWithFlags(&evFork, cudaEventDisableTiming);
    cudaEventCreateWithFlags(&evJoin, cudaEventDisableTiming);

    cudaEventRecord(evFork, 0);
    cudaStreamWaitEvent(side, evFork, 0);

    hist_kernel<<<(NE + 255) / 256, 256, 0, side>>>(dstp);
    scan1_kernel<<<98, 1024, 0, side>>>();
    scan2_kernel<<<1, 32, 0, side>>>();
    scan3_kernel<<<98, 1024, 0, side>>>();
    scatter_kernel<<<(NE + 255) / 256, 256, 0, side>>>(srcp, dstp);
    cudaEventRecord(evJoin, side);

    gemm_kernel<128><<<GB, 512, G128_SMEM>>>(x, 0, -1, gamma, beta);

    cudaStreamWaitEvent(0, evJoin, 0);

    agg_kernel<32, false><<<AB, 256>>>(nullptr, 0);
    gemm_kernel<128><<<GB, 512, G128_SMEM>>>(nullptr, 1, 0, gamma, beta);
    agg_kernel<32, false><<<AB, 256>>>(nullptr, 1);
    gemm_kernel<160><<<GB, 512, G160_SMEM>>>(nullptr, 2, 1, gamma + 128, beta + 128);
    agg_kernel<40, true><<<AB, 256>>>(out, 0);

    cudaStreamDestroy(side);
    cudaEventDestroy(evFork);
    cudaEventDestroy(evJoin);
}

// round 13
// speedup vs baseline: 1.3534x; 1.0641x over previous
#include <cuda_runtime.h>
#include <cuda_bf16.h>
#include <cuda_fp16.h>
#include <math_constants.h>
#include <cstdint>

#define NN 100000
#define NE 1600000

typedef unsigned long long ull;

// ---------------- device scratch ----------------
__device__ __half g_h16[NN * 160];     // h in fp16 (only consumer is the gather)
__device__ float  g_agg[NN * 128];
__device__ float4 g_as4[NN];
__device__ float4 g_ad4[NN];
__device__ int    g_deg[NN];
__device__ int    g_rowptr[NN + 1];
__device__ int    g_pos[NN];
__device__ int    g_srcs[NE];
__device__ __nv_bfloat16 g_Bh[3 * 22528];
__device__ __nv_bfloat16 g_Bl[3 * 22528];
__device__ float  g_thr;
__device__ float  g_bnsum[256], g_bnsq[256];   // ping-pong: buf0 (L0->L1), buf1 (L1->L2)
__device__ int    g_bsum[98], g_boff[98];

__device__ __forceinline__ float lrelu(float x) { return (x >= 0.f) ? x : 0.2f * x; }

__device__ __forceinline__ uint32_t smem_u32(const void* p) {
    uint32_t a;
    asm("{ .reg .u64 t; cvta.to.shared.u64 t, %1; cvt.u32.u64 %0, t; }" : "=r"(a) : "l"(p));
    return a;
}
__device__ __forceinline__ void ldmx4(uint32_t addr, uint32_t r[4]) {
    asm volatile("ldmatrix.sync.aligned.m8n8.x4.shared.b16 {%0,%1,%2,%3}, [%4];"
        : "=r"(r[0]), "=r"(r[1]), "=r"(r[2]), "=r"(r[3]) : "r"(addr));
}
__device__ __forceinline__ void ldmx2(uint32_t addr, uint32_t r[2]) {
    asm volatile("ldmatrix.sync.aligned.m8n8.x2.shared.b16 {%0,%1}, [%2];"
        : "=r"(r[0]), "=r"(r[1]) : "r"(addr));
}
__device__ __forceinline__ void mma_bf16(float c[4], const uint32_t a[4],
                                         uint32_t b0, uint32_t b1) {
    asm volatile("mma.sync.aligned.m16n8k16.row.col.f32.bf16.bf16.f32 "
        "{%0,%1,%2,%3}, {%4,%5,%6,%7}, {%8,%9}, {%0,%1,%2,%3};"
        : "+f"(c[0]), "+f"(c[1]), "+f"(c[2]), "+f"(c[3])
        : "r"(a[0]), "r"(a[1]), "r"(a[2]), "r"(a[3]), "r"(b0), "r"(b1));
}
__device__ __forceinline__ void bfsplit(float v, __nv_bfloat16& h, __nv_bfloat16& l) {
    h = __float2bfloat16(v);
    l = __float2bfloat16(v - __bfloat162float(h));
}

// ---------------- exact percentile (bitwise radix rank-select) ----------------
__global__ void thr_kernel(const float* __restrict__ s01, const float* __restrict__ s2) {
    extern __shared__ unsigned sm[];
    unsigned* red = sm + 53248;
    int t = threadIdx.x;
    for (int i = t; i < 32768; i += 1024) sm[i] = __float_as_uint(fabsf(s01[i]));
    for (int i = t; i < 20480; i += 1024) sm[32768 + i] = __float_as_uint(fabsf(s2[i]));
    __syncthreads();
    unsigned prefix = 0;
    int k = 26624;
    for (int bit = 30; bit >= 0; --bit) {
        unsigned himask = 0xFFFFFFFEu << bit;
        unsigned bitm = 1u << bit;
        int cnt = 0;
        for (int i = t; i < 53248; i += 1024) {
            unsigned v = sm[i];
            cnt += ((((v ^ prefix) & himask) == 0u) && ((v & bitm) == 0u)) ? 1 : 0;
        }
        #pragma unroll
        for (int o = 16; o; o >>= 1) cnt += __shfl_xor_sync(0xffffffffu, cnt, o);
        if ((t & 31) == 0) red[t >> 5] = (unsigned)cnt;
        __syncthreads();
        int total = 0;
        #pragma unroll
        for (int w = 0; w < 32; w++) total += (int)red[w];
        if (k >= total) { prefix |= bitm; k -= total; }
        __syncthreads();
    }
    if (t == 0) g_thr = __uint_as_float(prefix);
}

// ---------------- masked weights + attention-folded columns (merged) ----------
__global__ void __launch_bounds__(1024) maskwext_kernel(
        const float* __restrict__ w01, const float* __restrict__ s01,
        const float* __restrict__ att01,
        const float* __restrict__ w2, const float* __restrict__ s2,
        const float* __restrict__ att2) {
    float thr = g_thr;
    int b = blockIdx.x, t = threadIdx.x;
    if (b < 52) {
        int i = b * 1024 + t;
        if (i < 53248) {
            int L, k, n;
            float val;
            if (i < 16384) {
                L = 0; k = i >> 7; n = i & 127;
                val = (fabsf(s01[i]) < thr) ? 0.f : w01[i];
            } else if (i < 32768) {
                int j = i - 16384;
                L = 1; k = j >> 7; n = j & 127;
                val = (fabsf(s01[i]) < thr) ? 0.f : w01[i];
            } else {
                int j = i - 32768;
                L = 2; k = j / 160; n = j - k * 160;
                val = (fabsf(s2[j]) < thr) ? 0.f : w2[j];
            }
            __nv_bfloat16 hi, lo;
            bfsplit(val, hi, lo);
            int idx = L * 22528 + n * 128 + k;
            g_Bh[idx] = hi;
            g_Bl[idx] = lo;
        }
    } else {
        int k = t >> 3, slot = t & 7, sd = slot >> 2, h = slot & 3;
        #pragma unroll
        for (int L = 0; L < 2; L++) {
            float acc = 0.f;
            for (int d = 0; d < 32; d++) {
                int idx = L * 16384 + k * 128 + h * 32 + d;
                float w = (fabsf(s01[idx]) < thr) ? 0.f : w01[idx];
                acc = fmaf(w, att01[L * 256 + sd * 128 + h * 32 + d], acc);
            }
            __nv_bfloat16 hi, lo;
            bfsplit(acc, hi, lo);
            int idx2 = L * 22528 + (128 + slot) * 128 + k;
            g_Bh[idx2] = hi; g_Bl[idx2] = lo;
        }
        {
            float acc = 0.f;
            for (int d = 0; d < 40; d++) {
                int idx = k * 160 + h * 40 + d;
                float w = (fabsf(s2[idx]) < thr) ? 0.f : w2[idx];
                acc = fmaf(w, att2[sd * 160 + h * 40 + d], acc);
            }
            __nv_bfloat16 hi, lo;
            bfsplit(acc, hi, lo);
            int idx2 = 2 * 22528 + (160 + slot) * 128 + k;
            g_Bh[idx2] = hi; g_Bl[idx2] = lo;
        }
    }
}

// ---------------- CSR build ----------------
__global__ void hist_kernel(const int* __restrict__ dst) {
    int e = blockIdx.x * blockDim.x + threadIdx.x;
    if (e < NE) atomicAdd(&g_deg[dst[e]], 1);
}
__global__ void scan1_kernel() {
    __shared__ int red[32];
    int t = threadIdx.x, b = blockIdx.x;
    int i = b * 1024 + t;
    int s = (i < NN) ? g_deg[i] : 0;
    #pragma unroll
    for (int o = 16; o; o >>= 1) s += __shfl_xor_sync(0xffffffffu, s, o);
    if ((t & 31) == 0) red[t >> 5] = s;
    __syncthreads();
    if (t < 32) {
        int x = red[t];
        #pragma unroll
        for (int o = 16; o; o >>= 1) x += __shfl_xor_sync(0xffffffffu, x, o);
        if (t == 0) g_bsum[b] = x;
    }
}
__global__ void scan2_kernel() {
    if (threadIdx.x == 0) {
        int run = 0;
        for (int b = 0; b < 98; b++) { g_boff[b] = run; run += g_bsum[b]; }
        g_rowptr[NN] = run;
    }
}
__global__ void scan3_kernel() {
    __shared__ int sm[1024];
    int t = threadIdx.x, b = blockIdx.x;
    int i = b * 1024 + t;
    int v = (i < NN) ? g_deg[i] : 0;
    sm[t] = v;
    __syncthreads();
    for (int off = 1; off < 1024; off <<= 1) {
        int x = (t >= off) ? sm[t - off] : 0;
        __syncthreads();
        sm[t] += x;
        __syncthreads();
    }
    if (i < NN) {
        int excl = sm[t] - v + g_boff[b];
        g_rowptr[i] = excl;
        g_pos[i] = excl;
        g_deg[i] = 0;
    }
}
__global__ void scatter_kernel(const int* __restrict__ src, const int* __restrict__ dst) {
    int e = blockIdx.x * blockDim.x + threadIdx.x;
    if (blockIdx.x == 0 && threadIdx.x < 256) {
        g_bnsum[threadIdx.x] = 0.f;
        g_bnsq[threadIdx.x] = 0.f;
    }
    if (e < NE) {
        int d = dst[e];
        int p = atomicAdd(&g_pos[d], 1);
        g_srcs[p] = src[e];
    }
}

// ---------------- mma.sync bf16 GEMM, K-chunked (2 CTAs/SM), 512 threads ------
template<int NC>
__global__ void __launch_bounds__(512, 2) gemm_kernel(const float* __restrict__ Xopt,
                                                      int widx, int bnbuf,
                                                      const float* __restrict__ gamma,
                                                      const float* __restrict__ beta) {
    constexpr int NCP = NC + 8;
    constexpr int NT = NCP / 8;
    constexpr int NPAIRS = (NT + 1) / 2;
    constexpr int MAXP = (NPAIRS + 1) / 2;
    constexpr int KS = 72;
    extern __shared__ char dsm[];
    float* SC = (float*)dsm;
    float* SH = SC + 128;
    __nv_bfloat16* Ah = (__nv_bfloat16*)(dsm + 1024);
    __nv_bfloat16* Al = Ah + 128 * KS;
    __nv_bfloat16* Bh = Al + 128 * KS;
    __nv_bfloat16* Bl = Bh + NCP * KS;

    const int useBN = (bnbuf >= 0);
    const float* X = Xopt ? Xopt : g_agg;
    const int tid = threadIdx.x;
    const int wid = tid >> 5, lane = tid & 31;
    const int wy = wid & 7;
    const int wn = wid >> 3;
    const int row0 = blockIdx.x * 128;

    if (useBN && tid < 128) {
        float mu = g_bnsum[bnbuf * 128 + tid] * (1.f / NN);
        float var = g_bnsq[bnbuf * 128 + tid] * (1.f / NN) - mu * mu;
        float sc = rsqrtf(var + 1e-5f) * gamma[tid];
        SC[tid] = sc;
        SH[tid] = fmaf(-mu, sc, beta[tid]);
    }
    if (useBN) __syncthreads();

    float c[MAXP][2][4];
    #pragma unroll
    for (int pi = 0; pi < MAXP; pi++)
        #pragma unroll
        for (int u = 0; u < 2; u++)
            #pragma unroll
            for (int q = 0; q < 4; q++) c[pi][u][q] = 0.f;

    const uint32_t au = smem_u32(Ah), alu = smem_u32(Al);
    const uint32_t bu = smem_u32(Bh), blu = smem_u32(Bl);
    const int arow = wy * 16 + (lane & 15);
    const int acol0 = (lane >> 4) * 8;
    const int brow_x4 = (lane & 7) + ((lane >> 4) * 8);
    const int bcolsel = ((lane >> 3) & 1) * 8;

    for (int kc = 0; kc < 2; kc++) {
        {
            const char* sH = (const char*)(g_Bh + widx * 22528) + kc * 128;
            const char* sL = (const char*)(g_Bl + widx * 22528) + kc * 128;
            for (int i = tid; i < NCP * 8; i += 512) {
                int row = i >> 3, seg = i & 7;
                *(float4*)((char*)Bh + row * (KS * 2) + seg * 16) = *(const float4*)(sH + row * 256 + seg * 16);
                *(float4*)((char*)Bl + row * (KS * 2) + seg * 16) = *(const float4*)(sL + row * 256 + seg * 16);
            }
        }
        {
            __nv_bfloat162* A2h = (__nv_bfloat162*)Ah;
            __nv_bfloat162* A2l = (__nv_bfloat162*)Al;
            for (int i = tid; i < 2048; i += 512) {
                int r = i >> 4, c4l = i & 15;
                int c4 = kc * 16 + c4l;
                int gr = row0 + r;
                float4 v = make_float4(0.f, 0.f, 0.f, 0.f);
                if (gr < NN) {
                    v = ((const float4*)X)[gr * 32 + c4];
                    if (useBN) {
                        float4 sc = ((const float4*)SC)[c4];
                        float4 sh = ((const float4*)SH)[c4];
                        v.x = fmaxf(fmaf(v.x, sc.x, sh.x), 0.f);
                        v.y = fmaxf(fmaf(v.y, sc.y, sh.y), 0.f);
                        v.z = fmaxf(fmaf(v.z, sc.z, sh.z), 0.f);
                        v.w = fmaxf(fmaf(v.w, sc.w, sh.w), 0.f);
                    }
                }
                __nv_bfloat16 hx, lx, hy, ly, hz, lz, hw, lw;
                bfsplit(v.x, hx, lx); bfsplit(v.y, hy, ly);
                bfsplit(v.z, hz, lz); bfsplit(v.w, hw, lw);
                int o2 = r * (KS / 2) + c4l * 2;
                __nv_bfloat162 p0, p1, q0, q1;
                p0.x = hx; p0.y = hy; p1.x = hz; p1.y = hw;
                q0.x = lx; q0.y = ly; q1.x = lz; q1.y = lw;
                A2h[o2] = p0; A2h[o2 + 1] = p1;
                A2l[o2] = q0; A2l[o2 + 1] = q1;
            }
        }
        __syncthreads();

        for (int kb = 0; kb < 4; kb++) {
            uint32_t ah[4], al[4];
            uint32_t aoff = (uint32_t)((arow * KS + kb * 16 + acol0) * 2);
            ldmx4(au + aoff, ah);
            ldmx4(alu + aoff, al);
            #pragma unroll
            for (int pi = 0; pi < MAXP; pi++) {
                int p = wn + 2 * pi;
                if (p >= NPAIRS) break;
                if (2 * p + 1 < NT) {
                    uint32_t bh[4], bl[4];
                    uint32_t boff = (uint32_t)(((p * 16 + brow_x4) * KS + kb * 16 + bcolsel) * 2);
                    ldmx4(bu + boff, bh);
                    ldmx4(blu + boff, bl);
                    mma_bf16(c[pi][0], ah, bh[0], bh[1]);
                    mma_bf16(c[pi][0], ah, bl[0], bl[1]);
                    mma_bf16(c[pi][0], al, bh[0], bh[1]);
                    mma_bf16(c[pi][1], ah, bh[2], bh[3]);
                    mma_bf16(c[pi][1], ah, bl[2], bl[3]);
                    mma_bf16(c[pi][1], al, bh[2], bh[3]);
                } else {
                    uint32_t bh[2], bl[2];
                    int brow2 = 2 * p * 8 + (lane & 7);
                    uint32_t boff = (uint32_t)((brow2 * KS + kb * 16 + bcolsel) * 2);
                    ldmx2(bu + boff, bh);
                    ldmx2(blu + boff, bl);
                    mma_bf16(c[pi][0], ah, bh[0], bh[1]);
                    mma_bf16(c[pi][0], ah, bl[0], bl[1]);
                    mma_bf16(c[pi][0], al, bh[0], bh[1]);
                }
            }
        }
        __syncthreads();
    }

    const int g = lane >> 2, tig = lane & 3;
    const int rA = row0 + wy * 16 + g;
    const int rB = rA + 8;
    const bool okA = rA < NN, okB = rB < NN;
    #pragma unroll
    for (int pi = 0; pi < MAXP; pi++) {
        int p = wn + 2 * pi;
        if (p >= NPAIRS) break;
        #pragma unroll
        for (int u = 0; u < 2; u++) {
            int ntI = 2 * p + u;
            if (ntI >= NT) break;
            if (ntI < NT - 1) {
                if (okA) *(__half2*)&g_h16[rA * NC + ntI * 8 + tig * 2] =
                    __floats2half2_rn(c[pi][u][0], c[pi][u][1]);
                if (okB) *(__half2*)&g_h16[rB * NC + ntI * 8 + tig * 2] =
                    __floats2half2_rn(c[pi][u][2], c[pi][u][3]);
            } else {
                float e0 = c[pi][u][0], e1 = c[pi][u][1], e2 = c[pi][u][2], e3 = c[pi][u][3];
                float o0 = __shfl_xor_sync(0xffffffffu, e0, 1);
                float o1 = __shfl_xor_sync(0xffffffffu, e1, 1);
                float o2 = __shfl_xor_sync(0xffffffffu, e2, 1);
                float o3 = __shfl_xor_sync(0xffffffffu, e3, 1);
                if (tig == 0) {
                    if (okA) g_as4[rA] = make_float4(e0, e1, o0, o1);
                    if (okB) g_as4[rB] = make_float4(e2, e3, o2, o3);
                } else if (tig == 2) {
                    if (okA) g_ad4[rA] = make_float4(e0, e1, o0, o1);
                    if (okB) g_ad4[rB] = make_float4(e2, e3, o2, o3);
                }
            }
        }
    }
}

// ---------------- softmax + aggregation (warp per node, fp16 h gather) ---------
template<int C>
__device__ __forceinline__ void gather_step(int s, float alpha, float (&acc)[C], int lane) {
    if (C == 4) {
        uint2 hv = ((const uint2*)g_h16)[s * 32 + lane];   // 4 halves (cols lane*4..+3)
        float2 f0 = __half22float2(*reinterpret_cast<__half2*>(&hv.x));
        float2 f1 = __half22float2(*reinterpret_cast<__half2*>(&hv.y));
        acc[0] = fmaf(f0.x, alpha, acc[0]);
        acc[1] = fmaf(f0.y, alpha, acc[1]);
        acc[2] = fmaf(f1.x, alpha, acc[2]);
        acc[3] = fmaf(f1.y, alpha, acc[3]);
    } else {
        const __half* hr = g_h16 + s * (32 * C) + lane * C;
        #pragma unroll
        for (int j = 0; j < C; j++)
            acc[j] = fmaf(__half2float(hr[j]), alpha, acc[j]);
    }
}

template<int D, bool MEAN>
__global__ void __launch_bounds__(256) agg_kernel(float* __restrict__ outMean, int bnbuf) {
    constexpr int C = D / 8;
    __shared__ int    ssrc[8][64];
    __shared__ float4 ealpha[8][64];
    __shared__ float4 bnS[8][32];
    __shared__ float4 bnQ[8][32];
    int w = threadIdx.x >> 5, lane = threadIdx.x & 31;
    int v = blockIdx.x * 8 + w;
    int head = lane >> 3;
    int start = g_rowptr[v];
    int deg = g_rowptr[v + 1] - start;
    float4 ad = g_ad4[v];

    float acc[C];
    #pragma unroll
    for (int j = 0; j < C; j++) acc[j] = 0.f;

    if (deg > 0 && deg <= 64) {
        int s0 = 0, s1 = 0;
        float4 e0, e1;
        bool h0 = lane < deg, h1 = lane + 32 < deg;
        float m0 = -CUDART_INF_F, m1 = m0, m2 = m0, m3 = m0;
        if (h0) {
            s0 = g_srcs[start + lane];
            float4 a = g_as4[s0];
            e0.x = lrelu(a.x + ad.x); e0.y = lrelu(a.y + ad.y);
            e0.z = lrelu(a.z + ad.z); e0.w = lrelu(a.w + ad.w);
            m0 = e0.x; m1 = e0.y; m2 = e0.z; m3 = e0.w;
        }
        if (h1) {
            s1 = g_srcs[start + lane + 32];
            float4 a = g_as4[s1];
            e1.x = lrelu(a.x + ad.x); e1.y = lrelu(a.y + ad.y);
            e1.z = lrelu(a.z + ad.z); e1.w = lrelu(a.w + ad.w);
            m0 = fmaxf(m0, e1.x); m1 = fmaxf(m1, e1.y);
            m2 = fmaxf(m2, e1.z); m3 = fmaxf(m3, e1.w);
        }
        #pragma unroll
        for (int o = 16; o; o >>= 1) {
            m0 = fmaxf(m0, __shfl_xor_sync(0xffffffffu, m0, o));
            m1 = fmaxf(m1, __shfl_xor_sync(0xffffffffu, m1, o));
            m2 = fmaxf(m2, __shfl_xor_sync(0xffffffffu, m2, o));
            m3 = fmaxf(m3, __shfl_xor_sync(0xffffffffu, m3, o));
        }
        float d0 = 0.f, d1 = 0.f, d2 = 0.f, d3 = 0.f;
        float x00=0,x01=0,x02=0,x03=0, x10=0,x11=0,x12=0,x13=0;
        if (h0) {
            x00 = __expf(e0.x - m0); x01 = __expf(e0.y - m1);
            x02 = __expf(e0.z - m2); x03 = __expf(e0.w - m3);
            d0 += x00; d1 += x01; d2 += x02; d3 += x03;
        }
        if (h1) {
            x10 = __expf(e1.x - m0); x11 = __expf(e1.y - m1);
            x12 = __expf(e1.z - m2); x13 = __expf(e1.w - m3);
            d0 += x10; d1 += x11; d2 += x12; d3 += x13;
        }
        #pragma unroll
        for (int o = 16; o; o >>= 1) {
            d0 += __shfl_xor_sync(0xffffffffu, d0, o);
            d1 += __shfl_xor_sync(0xffffffffu, d1, o);
            d2 += __shfl_xor_sync(0xffffffffu, d2, o);
            d3 += __shfl_xor_sync(0xffffffffu, d3, o);
        }
        float i0 = 1.f / (d0 + 1e-16f), i1 = 1.f / (d1 + 1e-16f);
        float i2 = 1.f / (d2 + 1e-16f), i3 = 1.f / (d3 + 1e-16f);
        if (h0) {
            ssrc[w][lane] = s0;
            ealpha[w][lane] = make_float4(x00 * i0, x01 * i1, x02 * i2, x03 * i3);
        }
        if (h1) {
            ssrc[w][lane + 32] = s1;
            ealpha[w][lane + 32] = make_float4(x10 * i0, x11 * i1, x12 * i2, x13 * i3);
        }
        __syncwarp();
        #pragma unroll 4
        for (int t = 0; t < deg; t++) {
            int s = ssrc[w][t];
            float alpha = ((const float*)&ealpha[w][t])[head];
            gather_step<C>(s, alpha, acc, lane);
        }
    } else if (deg > 64) {
        float m0 = -CUDART_INF_F, m1 = m0, m2 = m0, m3 = m0;
        for (int i = lane; i < deg; i += 32) {
            int s = g_srcs[start + i];
            float4 a = g_as4[s];
            m0 = fmaxf(m0, lrelu(a.x + ad.x)); m1 = fmaxf(m1, lrelu(a.y + ad.y));
            m2 = fmaxf(m2, lrelu(a.z + ad.z)); m3 = fmaxf(m3, lrelu(a.w + ad.w));
        }
        #pragma unroll
        for (int o = 16; o; o >>= 1) {
            m0 = fmaxf(m0, __shfl_xor_sync(0xffffffffu, m0, o));
            m1 = fmaxf(m1, __shfl_xor_sync(0xffffffffu, m1, o));
            m2 = fmaxf(m2, __shfl_xor_sync(0xffffffffu, m2, o));
            m3 = fmaxf(m3, __shfl_xor_sync(0xffffffffu, m3, o));
        }
        float d0 = 0.f, d1 = 0.f, d2 = 0.f, d3 = 0.f;
        for (int i = lane; i < deg; i += 32) {
            int s = g_srcs[start + i];
            float4 a = g_as4[s];
            d0 += __expf(lrelu(a.x + ad.x) - m0);
            d1 += __expf(lrelu(a.y + ad.y) - m1);
            d2 += __expf(lrelu(a.z + ad.z) - m2);
            d3 += __expf(lrelu(a.w + ad.w) - m3);
        }
        #pragma unroll
        for (int o = 16; o; o >>= 1) {
            d0 += __shfl_xor_sync(0xffffffffu, d0, o);
            d1 += __shfl_xor_sync(0xffffffffu, d1, o);
            d2 += __shfl_xor_sync(0xffffffffu, d2, o);
            d3 += __shfl_xor_sync(0xffffffffu, d3, o);
        }
        float denh = (head == 0) ? d0 : (head == 1) ? d1 : (head == 2) ? d2 : d3;
        float mxh  = (head == 0) ? m0 : (head == 1) ? m1 : (head == 2) ? m2 : m3;
        float adh  = (head == 0) ? ad.x : (head == 1) ? ad.y : (head == 2) ? ad.z : ad.w;
        float invh = 1.f / (denh + 1e-16f);
        for (int t = 0; t < deg; t++) {
            int s = g_srcs[start + t];
            float ash = ((const float*)&g_as4[s])[head];
            float alpha = __expf(lrelu(ash + adh) - mxh) * invh;
            gather_step<C>(s, alpha, acc, lane);
        }
    }

    if (MEAN) {
        #pragma unroll
        for (int j = 0; j < C; j++) {
            float a = acc[j];
            a += __shfl_xor_sync(0xffffffffu, a, 8);
            a += __shfl_xor_sync(0xffffffffu, a, 16);
            if (lane < 8) outMean[v * D + lane * C + j] = 0.25f * a;
        }
    } else {
        float4 a4 = make_float4(acc[0], acc[1], acc[2], acc[3]);
        ((float4*)g_agg)[v * 32 + lane] = a4;
        bnS[w][lane] = a4;
        bnQ[w][lane] = make_float4(a4.x * a4.x, a4.y * a4.y, a4.z * a4.z, a4.w * a4.w);
        __syncthreads();
        int t = threadIdx.x;
        if (t < 128) {
            float s = 0.f;
            #pragma unroll
            for (int i = 0; i < 8; i++) s += ((const float*)&bnS[i][t >> 2])[t & 3];
            atomicAdd(&g_bnsum[bnbuf * 128 + t], s);
        } else {
            int cc = t - 128;
            float q = 0.f;
            #pragma unroll
            for (int i = 0; i < 8; i++) q += ((const float*)&bnQ[i][cc >> 2])[cc & 3];
            atomicAdd(&g_bnsq[bnbuf * 128 + cc], q);
        }
    }
}

// ---------------- launch ----------------
extern "C" void kernel_launch(void* const* d_in, const int* in_sizes, int n_in,
                              void* d_out, int out_size) {
    (void)in_sizes; (void)n_in; (void)out_size;
    const float* x     = (const float*)d_in[0];
    const int*   ei    = (const int*)d_in[1];
    const float* w01   = (const float*)d_in[2];
    const float* s01   = (const float*)d_in[3];
    const float* att01 = (const float*)d_in[4];
    const float* w2    = (const float*)d_in[5];
    const float* s2    = (const float*)d_in[6];
    const float* att2  = (const float*)d_in[7];
    const float* gamma = (const float*)d_in[8];
    const float* beta  = (const float*)d_in[9];
    float* out = (float*)d_out;
    const int* srcp = ei;
    const int* dstp = ei + NE;

    const int THR_SMEM  = (53248 + 32) * 4;
    const int G128_SMEM = 1024 + 2 * 128 * 72 * 2 + 2 * 136 * 72 * 2;   // ~75 KB
    const int G160_SMEM = 1024 + 2 * 128 * 72 * 2 + 2 * 168 * 72 * 2;   // ~84 KB
    cudaFuncSetAttribute(thr_kernel, cudaFuncAttributeMaxDynamicSharedMemorySize, THR_SMEM);
    cudaFuncSetAttribute(gemm_kernel<128>, cudaFuncAttributeMaxDynamicSharedMemorySize, G128_SMEM);
    cudaFuncSetAttribute(gemm_kernel<160>, cudaFuncAttributeMaxDynamicSharedMemorySize, G160_SMEM);

    const int GB = (NN + 127) / 128;   // 782
    const int AB = NN / 8;             // 12500 (warp per node)

    thr_kernel<<<1, 1024, THR_SMEM>>>(s01, s2);
    maskwext_kernel<<<53, 1024>>>(w01, s01, att01, w2, s2, att2);

    // Fork: CSR build on a side stream, concurrent with gemm L0.
    cudaStream_t side;
    cudaEvent_t evFork, evJoin;
    cudaStreamCreateWithFlags(&side, cudaStreamNonBlocking);
    cudaEventCreateWithFlags(&evFork, cudaEventDisableTiming);
    cudaEventCreateWithFlags(&evJoin, cudaEventDisableTiming);

    cudaEventRecord(evFork, 0);
    cudaStreamWaitEvent(side, evFork, 0);

    hist_kernel<<<(NE + 255) / 256, 256, 0, side>>>(dstp);
    scan1_kernel<<<98, 1024, 0, side>>>();
    scan2_kernel<<<1, 32, 0, side>>>();
    scan3_kernel<<<98, 1024, 0, side>>>();
    scatter_kernel<<<(NE + 255) / 256, 256, 0, side>>>(srcp, dstp);
    cudaEventRecord(evJoin, side);

    gemm_kernel<128><<<GB, 512, G128_SMEM>>>(x, 0, -1, gamma, beta);

    cudaStreamWaitEvent(0, evJoin, 0);

    agg_kernel<32, false><<<AB, 256>>>(nullptr, 0);
    gemm_kernel<128><<<GB, 512, G128_SMEM>>>(nullptr, 1, 0, gamma, beta);
    agg_kernel<32, false><<<AB, 256>>>(nullptr, 1);
    gemm_kernel<160><<<GB, 512, G160_SMEM>>>(nullptr, 2, 1, gamma + 128, beta + 128);
    agg_kernel<40, true><<<AB, 256>>>(out, 0);

    cudaStreamDestroy(side);
    cudaEventDestroy(evFork);
    cudaEventDestroy(evJoin);
}

// round 14
// speedup vs baseline: 1.5305x; 1.1309x over previous
#include <cuda_runtime.h>
#include <cuda_bf16.h>
#include <cuda_fp16.h>
#include <math_constants.h>
#include <cstdint>

#define NN 100000
#define NE 1600000

typedef unsigned long long ull;

// ---------------- device scratch ----------------
__device__ __half g_h16[NN * 160];     // h in fp16 (only consumer is the gather)
__device__ float  g_agg[NN * 128];
__device__ float4 g_as4[NN];
__device__ float4 g_ad4[NN];
__device__ int    g_deg[NN];
__device__ int    g_rowptr[NN + 1];
__device__ int    g_pos[NN];
__device__ int    g_srcs[NE];
__device__ __nv_bfloat16 g_Bh[3 * 22528];
__device__ __nv_bfloat16 g_Bl[3 * 22528];
__device__ float  g_thr;
__device__ float  g_bnsum[256], g_bnsq[256];   // ping-pong: buf0 (L0->L1), buf1 (L1->L2)
__device__ int    g_bsum[98], g_boff[98];

__device__ __forceinline__ float lrelu(float x) { return (x >= 0.f) ? x : 0.2f * x; }

__device__ __forceinline__ uint32_t smem_u32(const void* p) {
    uint32_t a;
    asm("{ .reg .u64 t; cvta.to.shared.u64 t, %1; cvt.u32.u64 %0, t; }" : "=r"(a) : "l"(p));
    return a;
}
__device__ __forceinline__ void ldmx4(uint32_t addr, uint32_t r[4]) {
    asm volatile("ldmatrix.sync.aligned.m8n8.x4.shared.b16 {%0,%1,%2,%3}, [%4];"
        : "=r"(r[0]), "=r"(r[1]), "=r"(r[2]), "=r"(r[3]) : "r"(addr));
}
__device__ __forceinline__ void ldmx2(uint32_t addr, uint32_t r[2]) {
    asm volatile("ldmatrix.sync.aligned.m8n8.x2.shared.b16 {%0,%1}, [%2];"
        : "=r"(r[0]), "=r"(r[1]) : "r"(addr));
}
__device__ __forceinline__ void mma_bf16(float c[4], const uint32_t a[4],
                                         uint32_t b0, uint32_t b1) {
    asm volatile("mma.sync.aligned.m16n8k16.row.col.f32.bf16.bf16.f32 "
        "{%0,%1,%2,%3}, {%4,%5,%6,%7}, {%8,%9}, {%0,%1,%2,%3};"
        : "+f"(c[0]), "+f"(c[1]), "+f"(c[2]), "+f"(c[3])
        : "r"(a[0]), "r"(a[1]), "r"(a[2]), "r"(a[3]), "r"(b0), "r"(b1));
}
__device__ __forceinline__ void bfsplit(float v, __nv_bfloat16& h, __nv_bfloat16& l) {
    h = __float2bfloat16(v);
    l = __float2bfloat16(v - __bfloat162float(h));
}

// ---------------- exact percentile: 15-bit histogram select (one kernel) ------
// rank k=26624 (0-based ascending) over 53248 |score| bit patterns.
__global__ void thr_kernel(const float* __restrict__ s01, const float* __restrict__ s2) {
    extern __shared__ unsigned sm[];
    unsigned* hist = sm;             // [32768]
    unsigned* tsum = sm + 32768;     // [1024]
    unsigned* misc = sm + 33792;     // [0]=bin, [1]=r, [2]=cnt
    unsigned* list = sm + 33808;     // [2048]
    const int t = threadIdx.x;
    const int K = 26624;

    #pragma unroll
    for (int j = 0; j < 32; j++) hist[t + j * 1024] = 0;
    if (t < 16) misc[t] = 0;
    __syncthreads();

    for (int i = t; i < 32768; i += 1024)
        atomicAdd(&hist[__float_as_uint(fabsf(s01[i])) >> 16], 1u);
    for (int i = t; i < 20480; i += 1024)
        atomicAdd(&hist[__float_as_uint(fabsf(s2[i])) >> 16], 1u);
    __syncthreads();

    // per-thread bin-group sums (32 bins each), inclusive scan over 1024
    unsigned s = 0;
    #pragma unroll
    for (int j = 0; j < 32; j++) s += hist[t * 32 + j];
    tsum[t] = s;
    __syncthreads();
    for (int off = 1; off < 1024; off <<= 1) {
        unsigned x = (t >= off) ? tsum[t - off] : 0u;
        __syncthreads();
        tsum[t] += x;
        __syncthreads();
    }
    {
        unsigned excl = (t == 0) ? 0u : tsum[t - 1];
        if ((unsigned)K >= excl && (unsigned)K < tsum[t]) {
            unsigned run = excl;
            #pragma unroll
            for (int j = 0; j < 32; j++) {
                unsigned c = hist[t * 32 + j];
                if ((unsigned)K < run + c) { misc[0] = (unsigned)(t * 32 + j); misc[1] = (unsigned)K - run; break; }
                run += c;
            }
        }
    }
    __syncthreads();
    const unsigned bin = misc[0], r = misc[1];

    // collect candidates in the selected bin
    for (int i = t; i < 32768; i += 1024) {
        unsigned u = __float_as_uint(fabsf(s01[i]));
        if ((u >> 16) == bin) {
            unsigned idx = atomicAdd(&misc[2], 1u);
            if (idx < 2048) list[idx] = u;
        }
    }
    for (int i = t; i < 20480; i += 1024) {
        unsigned u = __float_as_uint(fabsf(s2[i]));
        if ((u >> 16) == bin) {
            unsigned idx = atomicAdd(&misc[2], 1u);
            if (idx < 2048) list[idx] = u;
        }
    }
    __syncthreads();
    const int cnt = (int)min(misc[2], 2048u);
    for (int i = t; i < cnt; i += 1024) {
        unsigned v = list[i];
        int rank = 0;
        for (int j = 0; j < cnt; j++) {
            unsigned u = list[j];
            rank += (u < v) || (u == v && j < i);
        }
        if (rank == (int)r) g_thr = __uint_as_float(v);
    }
}

// ---------------- masked weights + attention-folded columns (merged) ----------
__global__ void __launch_bounds__(1024) maskwext_kernel(
        const float* __restrict__ w01, const float* __restrict__ s01,
        const float* __restrict__ att01,
        const float* __restrict__ w2, const float* __restrict__ s2,
        const float* __restrict__ att2) {
    float thr = g_thr;
    int b = blockIdx.x, t = threadIdx.x;
    if (b < 52) {
        int i = b * 1024 + t;
        if (i < 53248) {
            int L, k, n;
            float val;
            if (i < 16384) {
                L = 0; k = i >> 7; n = i & 127;
                val = (fabsf(s01[i]) < thr) ? 0.f : w01[i];
            } else if (i < 32768) {
                int j = i - 16384;
                L = 1; k = j >> 7; n = j & 127;
                val = (fabsf(s01[i]) < thr) ? 0.f : w01[i];
            } else {
                int j = i - 32768;
                L = 2; k = j / 160; n = j - k * 160;
                val = (fabsf(s2[j]) < thr) ? 0.f : w2[j];
            }
            __nv_bfloat16 hi, lo;
            bfsplit(val, hi, lo);
            int idx = L * 22528 + n * 128 + k;
            g_Bh[idx] = hi;
            g_Bl[idx] = lo;
        }
    } else {
        int k = t >> 3, slot = t & 7, sd = slot >> 2, h = slot & 3;
        #pragma unroll
        for (int L = 0; L < 2; L++) {
            float acc = 0.f;
            for (int d = 0; d < 32; d++) {
                int idx = L * 16384 + k * 128 + h * 32 + d;
                float w = (fabsf(s01[idx]) < thr) ? 0.f : w01[idx];
                acc = fmaf(w, att01[L * 256 + sd * 128 + h * 32 + d], acc);
            }
            __nv_bfloat16 hi, lo;
            bfsplit(acc, hi, lo);
            int idx2 = L * 22528 + (128 + slot) * 128 + k;
            g_Bh[idx2] = hi; g_Bl[idx2] = lo;
        }
        {
            float acc = 0.f;
            for (int d = 0; d < 40; d++) {
                int idx = k * 160 + h * 40 + d;
                float w = (fabsf(s2[idx]) < thr) ? 0.f : w2[idx];
                acc = fmaf(w, att2[sd * 160 + h * 40 + d], acc);
            }
            __nv_bfloat16 hi, lo;
            bfsplit(acc, hi, lo);
            int idx2 = 2 * 22528 + (160 + slot) * 128 + k;
            g_Bh[idx2] = hi; g_Bl[idx2] = lo;
        }
    }
}

// ---------------- CSR build ----------------
__global__ void hist_kernel(const int* __restrict__ dst) {
    int e = blockIdx.x * blockDim.x + threadIdx.x;
    if (e < NE) atomicAdd(&g_deg[dst[e]], 1);
}
__global__ void scan1_kernel() {
    __shared__ int red[32];
    int t = threadIdx.x, b = blockIdx.x;
    int i = b * 1024 + t;
    int s = (i < NN) ? g_deg[i] : 0;
    #pragma unroll
    for (int o = 16; o; o >>= 1) s += __shfl_xor_sync(0xffffffffu, s, o);
    if ((t & 31) == 0) red[t >> 5] = s;
    __syncthreads();
    if (t < 32) {
        int x = red[t];
        #pragma unroll
        for (int o = 16; o; o >>= 1) x += __shfl_xor_sync(0xffffffffu, x, o);
        if (t == 0) g_bsum[b] = x;
    }
}
__global__ void scan2_kernel() {
    if (threadIdx.x == 0) {
        int run = 0;
        for (int b = 0; b < 98; b++) { g_boff[b] = run; run += g_bsum[b]; }
        g_rowptr[NN] = run;
    }
}
__global__ void scan3_kernel() {
    __shared__ int sm[1024];
    int t = threadIdx.x, b = blockIdx.x;
    int i = b * 1024 + t;
    int v = (i < NN) ? g_deg[i] : 0;
    sm[t] = v;
    __syncthreads();
    for (int off = 1; off < 1024; off <<= 1) {
        int x = (t >= off) ? sm[t - off] : 0;
        __syncthreads();
        sm[t] += x;
        __syncthreads();
    }
    if (i < NN) {
        int excl = sm[t] - v + g_boff[b];
        g_rowptr[i] = excl;
        g_pos[i] = excl;
        g_deg[i] = 0;
    }
}
__global__ void scatter_kernel(const int* __restrict__ src, const int* __restrict__ dst) {
    int e = blockIdx.x * blockDim.x + threadIdx.x;
    if (blockIdx.x == 0 && threadIdx.x < 256) {
        g_bnsum[threadIdx.x] = 0.f;
        g_bnsq[threadIdx.x] = 0.f;
    }
    if (e < NE) {
        int d = dst[e];
        int p = atomicAdd(&g_pos[d], 1);
        g_srcs[p] = src[e];
    }
}

// ---------------- mma.sync bf16 GEMM, K-chunked (2 CTAs/SM), 512 threads ------
template<int NC>
__global__ void __launch_bounds__(512, 2) gemm_kernel(const float* __restrict__ Xopt,
                                                      int widx, int bnbuf,
                                                      const float* __restrict__ gamma,
                                                      const float* __restrict__ beta) {
    constexpr int NCP = NC + 8;
    constexpr int NT = NCP / 8;
    constexpr int NPAIRS = (NT + 1) / 2;
    constexpr int MAXP = (NPAIRS + 1) / 2;
    constexpr int KS = 72;
    extern __shared__ char dsm[];
    float* SC = (float*)dsm;
    float* SH = SC + 128;
    __nv_bfloat16* Ah = (__nv_bfloat16*)(dsm + 1024);
    __nv_bfloat16* Al = Ah + 128 * KS;
    __nv_bfloat16* Bh = Al + 128 * KS;
    __nv_bfloat16* Bl = Bh + NCP * KS;

    const int useBN = (bnbuf >= 0);
    const float* X = Xopt ? Xopt : g_agg;
    const int tid = threadIdx.x;
    const int wid = tid >> 5, lane = tid & 31;
    const int wy = wid & 7;
    const int wn = wid >> 3;
    const int row0 = blockIdx.x * 128;

    if (useBN && tid < 128) {
        float mu = g_bnsum[bnbuf * 128 + tid] * (1.f / NN);
        float var = g_bnsq[bnbuf * 128 + tid] * (1.f / NN) - mu * mu;
        float sc = rsqrtf(var + 1e-5f) * gamma[tid];
        SC[tid] = sc;
        SH[tid] = fmaf(-mu, sc, beta[tid]);
    }
    if (useBN) __syncthreads();

    float c[MAXP][2][4];
    #pragma unroll
    for (int pi = 0; pi < MAXP; pi++)
        #pragma unroll
        for (int u = 0; u < 2; u++)
            #pragma unroll
            for (int q = 0; q < 4; q++) c[pi][u][q] = 0.f;

    const uint32_t au = smem_u32(Ah), alu = smem_u32(Al);
    const uint32_t bu = smem_u32(Bh), blu = smem_u32(Bl);
    const int arow = wy * 16 + (lane & 15);
    const int acol0 = (lane >> 4) * 8;
    const int brow_x4 = (lane & 7) + ((lane >> 4) * 8);
    const int bcolsel = ((lane >> 3) & 1) * 8;

    for (int kc = 0; kc < 2; kc++) {
        {
            const char* sH = (const char*)(g_Bh + widx * 22528) + kc * 128;
            const char* sL = (const char*)(g_Bl + widx * 22528) + kc * 128;
            for (int i = tid; i < NCP * 8; i += 512) {
                int row = i >> 3, seg = i & 7;
                *(float4*)((char*)Bh + row * (KS * 2) + seg * 16) = *(const float4*)(sH + row * 256 + seg * 16);
                *(float4*)((char*)Bl + row * (KS * 2) + seg * 16) = *(const float4*)(sL + row * 256 + seg * 16);
            }
        }
        {
            __nv_bfloat162* A2h = (__nv_bfloat162*)Ah;
            __nv_bfloat162* A2l = (__nv_bfloat162*)Al;
            for (int i = tid; i < 2048; i += 512) {
                int r = i >> 4, c4l = i & 15;
                int c4 = kc * 16 + c4l;
                int gr = row0 + r;
                float4 v = make_float4(0.f, 0.f, 0.f, 0.f);
                if (gr < NN) {
                    v = ((const float4*)X)[gr * 32 + c4];
                    if (useBN) {
                        float4 sc = ((const float4*)SC)[c4];
                        float4 sh = ((const float4*)SH)[c4];
                        v.x = fmaxf(fmaf(v.x, sc.x, sh.x), 0.f);
                        v.y = fmaxf(fmaf(v.y, sc.y, sh.y), 0.f);
                        v.z = fmaxf(fmaf(v.z, sc.z, sh.z), 0.f);
                        v.w = fmaxf(fmaf(v.w, sc.w, sh.w), 0.f);
                    }
                }
                __nv_bfloat16 hx, lx, hy, ly, hz, lz, hw, lw;
                bfsplit(v.x, hx, lx); bfsplit(v.y, hy, ly);
                bfsplit(v.z, hz, lz); bfsplit(v.w, hw, lw);
                int o2 = r * (KS / 2) + c4l * 2;
                __nv_bfloat162 p0, p1, q0, q1;
                p0.x = hx; p0.y = hy; p1.x = hz; p1.y = hw;
                q0.x = lx; q0.y = ly; q1.x = lz; q1.y = lw;
                A2h[o2] = p0; A2h[o2 + 1] = p1;
                A2l[o2] = q0; A2l[o2 + 1] = q1;
            }
        }
        __syncthreads();

        for (int kb = 0; kb < 4; kb++) {
            uint32_t ah[4], al[4];
            uint32_t aoff = (uint32_t)((arow * KS + kb * 16 + acol0) * 2);
            ldmx4(au + aoff, ah);
            ldmx4(alu + aoff, al);
            #pragma unroll
            for (int pi = 0; pi < MAXP; pi++) {
                int p = wn + 2 * pi;
                if (p >= NPAIRS) break;
                if (2 * p + 1 < NT) {
                    uint32_t bh[4], bl[4];
                    uint32_t boff = (uint32_t)(((p * 16 + brow_x4) * KS + kb * 16 + bcolsel) * 2);
                    ldmx4(bu + boff, bh);
                    ldmx4(blu + boff, bl);
                    mma_bf16(c[pi][0], ah, bh[0], bh[1]);
                    mma_bf16(c[pi][0], ah, bl[0], bl[1]);
                    mma_bf16(c[pi][0], al, bh[0], bh[1]);
                    mma_bf16(c[pi][1], ah, bh[2], bh[3]);
                    mma_bf16(c[pi][1], ah, bl[2], bl[3]);
                    mma_bf16(c[pi][1], al, bh[2], bh[3]);
                } else {
                    uint32_t bh[2], bl[2];
                    int brow2 = 2 * p * 8 + (lane & 7);
                    uint32_t boff = (uint32_t)((brow2 * KS + kb * 16 + bcolsel) * 2);
                    ldmx2(bu + boff, bh);
                    ldmx2(blu + boff, bl);
                    mma_bf16(c[pi][0], ah, bh[0], bh[1]);
                    mma_bf16(c[pi][0], ah, bl[0], bl[1]);
                    mma_bf16(c[pi][0], al, bh[0], bh[1]);
                }
            }
        }
        __syncthreads();
    }

    const int g = lane >> 2, tig = lane & 3;
    const int rA = row0 + wy * 16 + g;
    const int rB = rA + 8;
    const bool okA = rA < NN, okB = rB < NN;
    #pragma unroll
    for (int pi = 0; pi < MAXP; pi++) {
        int p = wn + 2 * pi;
        if (p >= NPAIRS) break;
        #pragma unroll
        for (int u = 0; u < 2; u++) {
            int ntI = 2 * p + u;
            if (ntI >= NT) break;
            if (ntI < NT - 1) {
                if (okA) *(__half2*)&g_h16[rA * NC + ntI * 8 + tig * 2] =
                    __floats2half2_rn(c[pi][u][0], c[pi][u][1]);
                if (okB) *(__half2*)&g_h16[rB * NC + ntI * 8 + tig * 2] =
                    __floats2half2_rn(c[pi][u][2], c[pi][u][3]);
            } else {
                float e0 = c[pi][u][0], e1 = c[pi][u][1], e2 = c[pi][u][2], e3 = c[pi][u][3];
                float o0 = __shfl_xor_sync(0xffffffffu, e0, 1);
                float o1 = __shfl_xor_sync(0xffffffffu, e1, 1);
                float o2 = __shfl_xor_sync(0xffffffffu, e2, 1);
                float o3 = __shfl_xor_sync(0xffffffffu, e3, 1);
                if (tig == 0) {
                    if (okA) g_as4[rA] = make_float4(e0, e1, o0, o1);
                    if (okB) g_as4[rB] = make_float4(e2, e3, o2, o3);
                } else if (tig == 2) {
                    if (okA) g_ad4[rA] = make_float4(e0, e1, o0, o1);
                    if (okB) g_ad4[rB] = make_float4(e2, e3, o2, o3);
                }
            }
        }
    }
}

// ---------------- softmax + aggregation (warp/node, no max pass, fp16 gather) --
template<int C>
__device__ __forceinline__ void gather_step(int s, float alpha, float (&acc)[C], int lane) {
    if (C == 4) {
        uint2 hv = ((const uint2*)g_h16)[s * 32 + lane];
        float2 f0 = __half22float2(*reinterpret_cast<__half2*>(&hv.x));
        float2 f1 = __half22float2(*reinterpret_cast<__half2*>(&hv.y));
        acc[0] = fmaf(f0.x, alpha, acc[0]);
        acc[1] = fmaf(f0.y, alpha, acc[1]);
        acc[2] = fmaf(f1.x, alpha, acc[2]);
        acc[3] = fmaf(f1.y, alpha, acc[3]);
    } else {
        const __half* hr = g_h16 + s * (32 * C) + lane * C;
        #pragma unroll
        for (int j = 0; j < C; j++)
            acc[j] = fmaf(__half2float(hr[j]), alpha, acc[j]);
    }
}

template<int D, bool MEAN>
__global__ void __launch_bounds__(256) agg_kernel(float* __restrict__ outMean, int bnbuf) {
    constexpr int C = D / 8;
    __shared__ int    ssrc[8][64];
    __shared__ float4 ealpha[8][64];
    __shared__ float4 bnS[8][32];
    __shared__ float4 bnQ[8][32];
    int w = threadIdx.x >> 5, lane = threadIdx.x & 31;
    int v = blockIdx.x * 8 + w;
    int head = lane >> 3;
    int start = g_rowptr[v];
    int deg = g_rowptr[v + 1] - start;
    float4 ad = g_ad4[v];

    float acc[C];
    #pragma unroll
    for (int j = 0; j < C; j++) acc[j] = 0.f;

    if (deg > 0 && deg <= 64) {
        int s0 = 0, s1 = 0;
        bool h0 = lane < deg, h1 = lane + 32 < deg;
        float d0 = 0.f, d1 = 0.f, d2 = 0.f, d3 = 0.f;
        float x00=0,x01=0,x02=0,x03=0, x10=0,x11=0,x12=0,x13=0;
        if (h0) {
            s0 = g_srcs[start + lane];
            float4 a = g_as4[s0];
            x00 = __expf(lrelu(a.x + ad.x)); x01 = __expf(lrelu(a.y + ad.y));
            x02 = __expf(lrelu(a.z + ad.z)); x03 = __expf(lrelu(a.w + ad.w));
            d0 += x00; d1 += x01; d2 += x02; d3 += x03;
        }
        if (h1) {
            s1 = g_srcs[start + lane + 32];
            float4 a = g_as4[s1];
            x10 = __expf(lrelu(a.x + ad.x)); x11 = __expf(lrelu(a.y + ad.y));
            x12 = __expf(lrelu(a.z + ad.z)); x13 = __expf(lrelu(a.w + ad.w));
            d0 += x10; d1 += x11; d2 += x12; d3 += x13;
        }
        #pragma unroll
        for (int o = 16; o; o >>= 1) {
            d0 += __shfl_xor_sync(0xffffffffu, d0, o);
            d1 += __shfl_xor_sync(0xffffffffu, d1, o);
            d2 += __shfl_xor_sync(0xffffffffu, d2, o);
            d3 += __shfl_xor_sync(0xffffffffu, d3, o);
        }
        float i0 = 1.f / (d0 + 1e-16f), i1 = 1.f / (d1 + 1e-16f);
        float i2 = 1.f / (d2 + 1e-16f), i3 = 1.f / (d3 + 1e-16f);
        if (h0) {
            ssrc[w][lane] = s0;
            ealpha[w][lane] = make_float4(x00 * i0, x01 * i1, x02 * i2, x03 * i3);
        }
        if (h1) {
            ssrc[w][lane + 32] = s1;
            ealpha[w][lane + 32] = make_float4(x10 * i0, x11 * i1, x12 * i2, x13 * i3);
        }
        __syncwarp();
        #pragma unroll 4
        for (int t = 0; t < deg; t++) {
            int s = ssrc[w][t];
            float alpha = ((const float*)&ealpha[w][t])[head];
            gather_step<C>(s, alpha, acc, lane);
        }
    } else if (deg > 64) {
        float d0 = 0.f, d1 = 0.f, d2 = 0.f, d3 = 0.f;
        for (int i = lane; i < deg; i += 32) {
            int s = g_srcs[start + i];
            float4 a = g_as4[s];
            d0 += __expf(lrelu(a.x + ad.x));
            d1 += __expf(lrelu(a.y + ad.y));
            d2 += __expf(lrelu(a.z + ad.z));
            d3 += __expf(lrelu(a.w + ad.w));
        }
        #pragma unroll
        for (int o = 16; o; o >>= 1) {
            d0 += __shfl_xor_sync(0xffffffffu, d0, o);
            d1 += __shfl_xor_sync(0xffffffffu, d1, o);
            d2 += __shfl_xor_sync(0xffffffffu, d2, o);
            d3 += __shfl_xor_sync(0xffffffffu, d3, o);
        }
        float denh = (head == 0) ? d0 : (head == 1) ? d1 : (head == 2) ? d2 : d3;
        float adh  = (head == 0) ? ad.x : (head == 1) ? ad.y : (head == 2) ? ad.z : ad.w;
        float invh = 1.f / (denh + 1e-16f);
        for (int t = 0; t < deg; t++) {
            int s = g_srcs[start + t];
            float ash = ((const float*)&g_as4[s])[head];
            float alpha = __expf(lrelu(ash + adh)) * invh;
            gather_step<C>(s, alpha, acc, lane);
        }
    }

    if (MEAN) {
        #pragma unroll
        for (int j = 0; j < C; j++) {
            float a = acc[j];
            a += __shfl_xor_sync(0xffffffffu, a, 8);
            a += __shfl_xor_sync(0xffffffffu, a, 16);
            if (lane < 8) outMean[v * D + lane * C + j] = 0.25f * a;
        }
    } else {
        float4 a4 = make_float4(acc[0], acc[1], acc[2], acc[3]);
        ((float4*)g_agg)[v * 32 + lane] = a4;
        bnS[w][lane] = a4;
        bnQ[w][lane] = make_float4(a4.x * a4.x, a4.y * a4.y, a4.z * a4.z, a4.w * a4.w);
        __syncthreads();
        int t = threadIdx.x;
        if (t < 128) {
            float s = 0.f;
            #pragma unroll
            for (int i = 0; i < 8; i++) s += ((const float*)&bnS[i][t >> 2])[t & 3];
            atomicAdd(&g_bnsum[bnbuf * 128 + t], s);
        } else {
            int cc = t - 128;
            float q = 0.f;
            #pragma unroll
            for (int i = 0; i < 8; i++) q += ((const float*)&bnQ[i][cc >> 2])[cc & 3];
            atomicAdd(&g_bnsq[bnbuf * 128 + cc], q);
        }
    }
}

// ---------------- launch ----------------
extern "C" void kernel_launch(void* const* d_in, const int* in_sizes, int n_in,
                              void* d_out, int out_size) {
    (void)in_sizes; (void)n_in; (void)out_size;
    const float* x     = (const float*)d_in[0];
    const int*   ei    = (const int*)d_in[1];
    const float* w01   = (const float*)d_in[2];
    const float* s01   = (const float*)d_in[3];
    const float* att01 = (const float*)d_in[4];
    const float* w2    = (const float*)d_in[5];
    const float* s2    = (const float*)d_in[6];
    const float* att2  = (const float*)d_in[7];
    const float* gamma = (const float*)d_in[8];
    const float* beta  = (const float*)d_in[9];
    float* out = (float*)d_out;
    const int* srcp = ei;
    const int* dstp = ei + NE;

    const int THR_SMEM  = (32768 + 1024 + 16 + 2048) * 4;               // ~140 KB
    const int G128_SMEM = 1024 + 2 * 128 * 72 * 2 + 2 * 136 * 72 * 2;   // ~75 KB
    const int G160_SMEM = 1024 + 2 * 128 * 72 * 2 + 2 * 168 * 72 * 2;   // ~84 KB
    cudaFuncSetAttribute(thr_kernel, cudaFuncAttributeMaxDynamicSharedMemorySize, THR_SMEM);
    cudaFuncSetAttribute(gemm_kernel<128>, cudaFuncAttributeMaxDynamicSharedMemorySize, G128_SMEM);
    cudaFuncSetAttribute(gemm_kernel<160>, cudaFuncAttributeMaxDynamicSharedMemorySize, G160_SMEM);

    const int GB = (NN + 127) / 128;   // 782
    const int AB = NN / 8;             // 12500 (warp per node)

    // Fork CSR side stream at the very start (no dependence on thr/mask).
    cudaStream_t side;
    cudaEvent_t evFork, evJoin;
    cudaStreamCreateWithFlags(&side, cudaStreamNonBlocking);
    cudaEventCreateWithFlags(&evFork, cudaEventDisableTiming);
    cudaEventCreateWithFlags(&evJoin, cudaEventDisableTiming);

    cudaEventRecord(evFork, 0);
    cudaStreamWaitEvent(side, evFork, 0);

    hist_kernel<<<(NE + 255) / 256, 256, 0, side>>>(dstp);
    scan1_kernel<<<98, 1024, 0, side>>>();
    scan2_kernel<<<1, 32, 0, side>>>();
    scan3_kernel<<<98, 1024, 0, side>>>();
    scatter_kernel<<<(NE + 255) / 256, 256, 0, side>>>(srcp, dstp);
    cudaEventRecord(evJoin, side);

    // main: threshold -> masked weights -> gemm L0
    thr_kernel<<<1, 1024, THR_SMEM>>>(s01, s2);
    maskwext_kernel<<<53, 1024>>>(w01, s01, att01, w2, s2, att2);
    gemm_kernel<128><<<GB, 512, G128_SMEM>>>(x, 0, -1, gamma, beta);

    cudaStreamWaitEvent(0, evJoin, 0);

    agg_kernel<32, false><<<AB, 256>>>(nullptr, 0);
    gemm_kernel<128><<<GB, 512, G128_SMEM>>>(nullptr, 1, 0, gamma, beta);
    agg_kernel<32, false><<<AB, 256>>>(nullptr, 1);
    gemm_kernel<160><<<GB, 512, G160_SMEM>>>(nullptr, 2, 1, gamma + 128, beta + 128);
    agg_kernel<40, true><<<AB, 256>>>(out, 0);

    cudaStreamDestroy(side);
    cudaEventDestroy(evFork);
    cudaEventDestroy(evJoin);
}

// round 15
// speedup vs baseline: 1.5590x; 1.0186x over previous
#include <cuda_runtime.h>
#include <cuda_bf16.h>
#include <cuda_fp16.h>
#include <math_constants.h>
#include <cstdint>

#define NN 100000
#define NE 1600000

typedef unsigned long long ull;

// ---------------- device scratch ----------------
__device__ __half g_h16[NN * 160];     // h in fp16 (only consumer is the gather)
__device__ float  g_agg[NN * 128];
__device__ float4 g_as4[NN];
__device__ float4 g_ad4[NN];
__device__ int    g_deg[NN];
__device__ int    g_rowptr[NN + 1];
__device__ int    g_pos[NN];
__device__ int    g_srcs[NE];
__device__ __nv_bfloat16 g_Bh[3 * 22528];
__device__ __nv_bfloat16 g_Bl[3 * 22528];
__device__ float  g_thr;
__device__ float  g_bnsum[256], g_bnsq[256];   // ping-pong: buf0 (L0->L1), buf1 (L1->L2)
__device__ int    g_bsum[98], g_boff[98];

__device__ __forceinline__ float lrelu(float x) { return (x >= 0.f) ? x : 0.2f * x; }

__device__ __forceinline__ uint32_t smem_u32(const void* p) {
    uint32_t a;
    asm("{ .reg .u64 t; cvta.to.shared.u64 t, %1; cvt.u32.u64 %0, t; }" : "=r"(a) : "l"(p));
    return a;
}
__device__ __forceinline__ void ldmx4(uint32_t addr, uint32_t r[4]) {
    asm volatile("ldmatrix.sync.aligned.m8n8.x4.shared.b16 {%0,%1,%2,%3}, [%4];"
        : "=r"(r[0]), "=r"(r[1]), "=r"(r[2]), "=r"(r[3]) : "r"(addr));
}
__device__ __forceinline__ void ldmx2(uint32_t addr, uint32_t r[2]) {
    asm volatile("ldmatrix.sync.aligned.m8n8.x2.shared.b16 {%0,%1}, [%2];"
        : "=r"(r[0]), "=r"(r[1]) : "r"(addr));
}
__device__ __forceinline__ void mma_bf16(float c[4], const uint32_t a[4],
                                         uint32_t b0, uint32_t b1) {
    asm volatile("mma.sync.aligned.m16n8k16.row.col.f32.bf16.bf16.f32 "
        "{%0,%1,%2,%3}, {%4,%5,%6,%7}, {%8,%9}, {%0,%1,%2,%3};"
        : "+f"(c[0]), "+f"(c[1]), "+f"(c[2]), "+f"(c[3])
        : "r"(a[0]), "r"(a[1]), "r"(a[2]), "r"(a[3]), "r"(b0), "r"(b1));
}
__device__ __forceinline__ void bfsplit(float v, __nv_bfloat16& h, __nv_bfloat16& l) {
    h = __float2bfloat16(v);
    l = __float2bfloat16(v - __bfloat162float(h));
}

// ---------------- exact percentile: 15-bit histogram select ----------------
__global__ void thr_kernel(const float* __restrict__ s01, const float* __restrict__ s2) {
    extern __shared__ unsigned sm[];
    unsigned* hist = sm;             // [32768]
    unsigned* tsum = sm + 32768;     // [1024]
    unsigned* misc = sm + 33792;     // [0]=bin, [1]=r, [2]=cnt
    unsigned* list = sm + 33808;     // [2048]
    const int t = threadIdx.x;
    const int K = 26624;

    #pragma unroll
    for (int j = 0; j < 32; j++) hist[t + j * 1024] = 0;
    if (t < 16) misc[t] = 0;
    __syncthreads();

    for (int i = t; i < 32768; i += 1024)
        atomicAdd(&hist[__float_as_uint(fabsf(s01[i])) >> 16], 1u);
    for (int i = t; i < 20480; i += 1024)
        atomicAdd(&hist[__float_as_uint(fabsf(s2[i])) >> 16], 1u);
    __syncthreads();

    unsigned s = 0;
    #pragma unroll
    for (int j = 0; j < 32; j++) s += hist[t * 32 + j];
    tsum[t] = s;
    __syncthreads();
    for (int off = 1; off < 1024; off <<= 1) {
        unsigned x = (t >= off) ? tsum[t - off] : 0u;
        __syncthreads();
        tsum[t] += x;
        __syncthreads();
    }
    {
        unsigned excl = (t == 0) ? 0u : tsum[t - 1];
        if ((unsigned)K >= excl && (unsigned)K < tsum[t]) {
            unsigned run = excl;
            #pragma unroll
            for (int j = 0; j < 32; j++) {
                unsigned c = hist[t * 32 + j];
                if ((unsigned)K < run + c) { misc[0] = (unsigned)(t * 32 + j); misc[1] = (unsigned)K - run; break; }
                run += c;
            }
        }
    }
    __syncthreads();
    const unsigned bin = misc[0], r = misc[1];

    for (int i = t; i < 32768; i += 1024) {
        unsigned u = __float_as_uint(fabsf(s01[i]));
        if ((u >> 16) == bin) {
            unsigned idx = atomicAdd(&misc[2], 1u);
            if (idx < 2048) list[idx] = u;
        }
    }
    for (int i = t; i < 20480; i += 1024) {
        unsigned u = __float_as_uint(fabsf(s2[i]));
        if ((u >> 16) == bin) {
            unsigned idx = atomicAdd(&misc[2], 1u);
            if (idx < 2048) list[idx] = u;
        }
    }
    __syncthreads();
    const int cnt = (int)min(misc[2], 2048u);
    for (int i = t; i < cnt; i += 1024) {
        unsigned v = list[i];
        int rank = 0;
        for (int j = 0; j < cnt; j++) {
            unsigned u = list[j];
            rank += (u < v) || (u == v && j < i);
        }
        if (rank == (int)r) g_thr = __uint_as_float(v);
    }
}

// ---------------- masked weights + attention-folded columns (merged) ----------
__global__ void __launch_bounds__(1024) maskwext_kernel(
        const float* __restrict__ w01, const float* __restrict__ s01,
        const float* __restrict__ att01,
        const float* __restrict__ w2, const float* __restrict__ s2,
        const float* __restrict__ att2) {
    float thr = g_thr;
    int b = blockIdx.x, t = threadIdx.x;
    if (b < 52) {
        int i = b * 1024 + t;
        if (i < 53248) {
            int L, k, n;
            float val;
            if (i < 16384) {
                L = 0; k = i >> 7; n = i & 127;
                val = (fabsf(s01[i]) < thr) ? 0.f : w01[i];
            } else if (i < 32768) {
                int j = i - 16384;
                L = 1; k = j >> 7; n = j & 127;
                val = (fabsf(s01[i]) < thr) ? 0.f : w01[i];
            } else {
                int j = i - 32768;
                L = 2; k = j / 160; n = j - k * 160;
                val = (fabsf(s2[j]) < thr) ? 0.f : w2[j];
            }
            __nv_bfloat16 hi, lo;
            bfsplit(val, hi, lo);
            int idx = L * 22528 + n * 128 + k;
            g_Bh[idx] = hi;
            g_Bl[idx] = lo;
        }
    } else {
        int k = t >> 3, slot = t & 7, sd = slot >> 2, h = slot & 3;
        #pragma unroll
        for (int L = 0; L < 2; L++) {
            float acc = 0.f;
            for (int d = 0; d < 32; d++) {
                int idx = L * 16384 + k * 128 + h * 32 + d;
                float w = (fabsf(s01[idx]) < thr) ? 0.f : w01[idx];
                acc = fmaf(w, att01[L * 256 + sd * 128 + h * 32 + d], acc);
            }
            __nv_bfloat16 hi, lo;
            bfsplit(acc, hi, lo);
            int idx2 = L * 22528 + (128 + slot) * 128 + k;
            g_Bh[idx2] = hi; g_Bl[idx2] = lo;
        }
        {
            float acc = 0.f;
            for (int d = 0; d < 40; d++) {
                int idx = k * 160 + h * 40 + d;
                float w = (fabsf(s2[idx]) < thr) ? 0.f : w2[idx];
                acc = fmaf(w, att2[sd * 160 + h * 40 + d], acc);
            }
            __nv_bfloat16 hi, lo;
            bfsplit(acc, hi, lo);
            int idx2 = 2 * 22528 + (160 + slot) * 128 + k;
            g_Bh[idx2] = hi; g_Bl[idx2] = lo;
        }
    }
}

// ---------------- CSR build ----------------
__global__ void hist_kernel(const int* __restrict__ dst) {
    int e = blockIdx.x * blockDim.x + threadIdx.x;
    if (e < NE) atomicAdd(&g_deg[dst[e]], 1);
}
__global__ void scan1_kernel() {
    __shared__ int red[32];
    int t = threadIdx.x, b = blockIdx.x;
    int i = b * 1024 + t;
    int s = (i < NN) ? g_deg[i] : 0;
    #pragma unroll
    for (int o = 16; o; o >>= 1) s += __shfl_xor_sync(0xffffffffu, s, o);
    if ((t & 31) == 0) red[t >> 5] = s;
    __syncthreads();
    if (t < 32) {
        int x = red[t];
        #pragma unroll
        for (int o = 16; o; o >>= 1) x += __shfl_xor_sync(0xffffffffu, x, o);
        if (t == 0) g_bsum[b] = x;
    }
}
__global__ void scan2_kernel() {
    if (threadIdx.x == 0) {
        int run = 0;
        for (int b = 0; b < 98; b++) { g_boff[b] = run; run += g_bsum[b]; }
        g_rowptr[NN] = run;
    }
}
__global__ void scan3_kernel() {
    __shared__ int sm[1024];
    int t = threadIdx.x, b = blockIdx.x;
    int i = b * 1024 + t;
    int v = (i < NN) ? g_deg[i] : 0;
    sm[t] = v;
    __syncthreads();
    for (int off = 1; off < 1024; off <<= 1) {
        int x = (t >= off) ? sm[t - off] : 0;
        __syncthreads();
        sm[t] += x;
        __syncthreads();
    }
    if (i < NN) {
        int excl = sm[t] - v + g_boff[b];
        g_rowptr[i] = excl;
        g_pos[i] = excl;
        g_deg[i] = 0;
    }
}
__global__ void scatter_kernel(const int* __restrict__ src, const int* __restrict__ dst) {
    int e = blockIdx.x * blockDim.x + threadIdx.x;
    if (blockIdx.x == 0 && threadIdx.x < 256) {
        g_bnsum[threadIdx.x] = 0.f;
        g_bnsq[threadIdx.x] = 0.f;
    }
    if (e < NE) {
        int d = dst[e];
        int p = atomicAdd(&g_pos[d], 1);
        g_srcs[p] = src[e];
    }
}

// ---------------- mma.sync bf16 GEMM, K-chunked (2 CTAs/SM), 512 threads ------
template<int NC>
__global__ void __launch_bounds__(512, 2) gemm_kernel(const float* __restrict__ Xopt,
                                                      int widx, int bnbuf,
                                                      const float* __restrict__ gamma,
                                                      const float* __restrict__ beta) {
    constexpr int NCP = NC + 8;
    constexpr int NT = NCP / 8;
    constexpr int NPAIRS = (NT + 1) / 2;
    constexpr int MAXP = (NPAIRS + 1) / 2;
    constexpr int KS = 72;
    extern __shared__ char dsm[];
    float* SC = (float*)dsm;
    float* SH = SC + 128;
    __nv_bfloat16* Ah = (__nv_bfloat16*)(dsm + 1024);
    __nv_bfloat16* Al = Ah + 128 * KS;
    __nv_bfloat16* Bh = Al + 128 * KS;
    __nv_bfloat16* Bl = Bh + NCP * KS;

    const int useBN = (bnbuf >= 0);
    const float* X = Xopt ? Xopt : g_agg;
    const int tid = threadIdx.x;
    const int wid = tid >> 5, lane = tid & 31;
    const int wy = wid & 7;
    const int wn = wid >> 3;
    const int row0 = blockIdx.x * 128;

    if (useBN && tid < 128) {
        float mu = g_bnsum[bnbuf * 128 + tid] * (1.f / NN);
        float var = g_bnsq[bnbuf * 128 + tid] * (1.f / NN) - mu * mu;
        float sc = rsqrtf(var + 1e-5f) * gamma[tid];
        SC[tid] = sc;
        SH[tid] = fmaf(-mu, sc, beta[tid]);
    }
    if (useBN) __syncthreads();

    float c[MAXP][2][4];
    #pragma unroll
    for (int pi = 0; pi < MAXP; pi++)
        #pragma unroll
        for (int u = 0; u < 2; u++)
            #pragma unroll
            for (int q = 0; q < 4; q++) c[pi][u][q] = 0.f;

    const uint32_t au = smem_u32(Ah), alu = smem_u32(Al);
    const uint32_t bu = smem_u32(Bh), blu = smem_u32(Bl);
    const int arow = wy * 16 + (lane & 15);
    const int acol0 = (lane >> 4) * 8;
    const int brow_x4 = (lane & 7) + ((lane >> 4) * 8);
    const int bcolsel = ((lane >> 3) & 1) * 8;

    for (int kc = 0; kc < 2; kc++) {
        {
            const char* sH = (const char*)(g_Bh + widx * 22528) + kc * 128;
            const char* sL = (const char*)(g_Bl + widx * 22528) + kc * 128;
            for (int i = tid; i < NCP * 8; i += 512) {
                int row = i >> 3, seg = i & 7;
                *(float4*)((char*)Bh + row * (KS * 2) + seg * 16) = *(const float4*)(sH + row * 256 + seg * 16);
                *(float4*)((char*)Bl + row * (KS * 2) + seg * 16) = *(const float4*)(sL + row * 256 + seg * 16);
            }
        }
        {
            __nv_bfloat162* A2h = (__nv_bfloat162*)Ah;
            __nv_bfloat162* A2l = (__nv_bfloat162*)Al;
            for (int i = tid; i < 2048; i += 512) {
                int r = i >> 4, c4l = i & 15;
                int c4 = kc * 16 + c4l;
                int gr = row0 + r;
                float4 v = make_float4(0.f, 0.f, 0.f, 0.f);
                if (gr < NN) {
                    v = ((const float4*)X)[gr * 32 + c4];
                    if (useBN) {
                        float4 sc = ((const float4*)SC)[c4];
                        float4 sh = ((const float4*)SH)[c4];
                        v.x = fmaxf(fmaf(v.x, sc.x, sh.x), 0.f);
                        v.y = fmaxf(fmaf(v.y, sc.y, sh.y), 0.f);
                        v.z = fmaxf(fmaf(v.z, sc.z, sh.z), 0.f);
                        v.w = fmaxf(fmaf(v.w, sc.w, sh.w), 0.f);
                    }
                }
                __nv_bfloat16 hx, lx, hy, ly, hz, lz, hw, lw;
                bfsplit(v.x, hx, lx); bfsplit(v.y, hy, ly);
                bfsplit(v.z, hz, lz); bfsplit(v.w, hw, lw);
                int o2 = r * (KS / 2) + c4l * 2;
                __nv_bfloat162 p0, p1, q0, q1;
                p0.x = hx; p0.y = hy; p1.x = hz; p1.y = hw;
                q0.x = lx; q0.y = ly; q1.x = lz; q1.y = lw;
                A2h[o2] = p0; A2h[o2 + 1] = p1;
                A2l[o2] = q0; A2l[o2 + 1] = q1;
            }
        }
        __syncthreads();

        for (int kb = 0; kb < 4; kb++) {
            uint32_t ah[4], al[4];
            uint32_t aoff = (uint32_t)((arow * KS + kb * 16 + acol0) * 2);
            ldmx4(au + aoff, ah);
            ldmx4(alu + aoff, al);
            #pragma unroll
            for (int pi = 0; pi < MAXP; pi++) {
                int p = wn + 2 * pi;
                if (p >= NPAIRS) break;
                if (2 * p + 1 < NT) {
                    uint32_t bh[4], bl[4];
                    uint32_t boff = (uint32_t)(((p * 16 + brow_x4) * KS + kb * 16 + bcolsel) * 2);
                    ldmx4(bu + boff, bh);
                    ldmx4(blu + boff, bl);
                    mma_bf16(c[pi][0], ah, bh[0], bh[1]);
                    mma_bf16(c[pi][0], ah, bl[0], bl[1]);
                    mma_bf16(c[pi][0], al, bh[0], bh[1]);
                    mma_bf16(c[pi][1], ah, bh[2], bh[3]);
                    mma_bf16(c[pi][1], ah, bl[2], bl[3]);
                    mma_bf16(c[pi][1], al, bh[2], bh[3]);
                } else {
                    uint32_t bh[2], bl[2];
                    int brow2 = 2 * p * 8 + (lane & 7);
                    uint32_t boff = (uint32_t)((brow2 * KS + kb * 16 + bcolsel) * 2);
                    ldmx2(bu + boff, bh);
                    ldmx2(blu + boff, bl);
                    mma_bf16(c[pi][0], ah, bh[0], bh[1]);
                    mma_bf16(c[pi][0], ah, bl[0], bl[1]);
                    mma_bf16(c[pi][0], al, bh[0], bh[1]);
                }
            }
        }
        __syncthreads();
    }

    const int g = lane >> 2, tig = lane & 3;
    const int rA = row0 + wy * 16 + g;
    const int rB = rA + 8;
    const bool okA = rA < NN, okB = rB < NN;
    #pragma unroll
    for (int pi = 0; pi < MAXP; pi++) {
        int p = wn + 2 * pi;
        if (p >= NPAIRS) break;
        #pragma unroll
        for (int u = 0; u < 2; u++) {
            int ntI = 2 * p + u;
            if (ntI >= NT) break;
            if (ntI < NT - 1) {
                if (okA) *(__half2*)&g_h16[rA * NC + ntI * 8 + tig * 2] =
                    __floats2half2_rn(c[pi][u][0], c[pi][u][1]);
                if (okB) *(__half2*)&g_h16[rB * NC + ntI * 8 + tig * 2] =
                    __floats2half2_rn(c[pi][u][2], c[pi][u][3]);
            } else {
                float e0 = c[pi][u][0], e1 = c[pi][u][1], e2 = c[pi][u][2], e3 = c[pi][u][3];
                float o0 = __shfl_xor_sync(0xffffffffu, e0, 1);
                float o1 = __shfl_xor_sync(0xffffffffu, e1, 1);
                float o2 = __shfl_xor_sync(0xffffffffu, e2, 1);
                float o3 = __shfl_xor_sync(0xffffffffu, e3, 1);
                if (tig == 0) {
                    if (okA) g_as4[rA] = make_float4(e0, e1, o0, o1);
                    if (okB) g_as4[rB] = make_float4(e2, e3, o2, o3);
                } else if (tig == 2) {
                    if (okA) g_ad4[rA] = make_float4(e0, e1, o0, o1);
                    if (okB) g_ad4[rB] = make_float4(e2, e3, o2, o3);
                }
            }
        }
    }
}

// ---------------- agg for layers 0/1 (NC=128, warp/node, fp16 gather) ----------
__global__ void __launch_bounds__(256) agg_kernel(int bnbuf) {
    __shared__ int    ssrc[8][64];
    __shared__ float4 ealpha[8][64];
    __shared__ float4 bnS[8][32];
    __shared__ float4 bnQ[8][32];
    int w = threadIdx.x >> 5, lane = threadIdx.x & 31;
    int v = blockIdx.x * 8 + w;
    int head = lane >> 3;
    int start = g_rowptr[v];
    int deg = g_rowptr[v + 1] - start;
    float4 ad = g_ad4[v];

    float acc[4] = {0.f, 0.f, 0.f, 0.f};

    if (deg > 0 && deg <= 64) {
        int s0 = 0, s1 = 0;
        bool h0 = lane < deg, h1 = lane + 32 < deg;
        float d0 = 0.f, d1 = 0.f, d2 = 0.f, d3 = 0.f;
        float x00=0,x01=0,x02=0,x03=0, x10=0,x11=0,x12=0,x13=0;
        if (h0) {
            s0 = g_srcs[start + lane];
            float4 a = g_as4[s0];
            x00 = __expf(lrelu(a.x + ad.x)); x01 = __expf(lrelu(a.y + ad.y));
            x02 = __expf(lrelu(a.z + ad.z)); x03 = __expf(lrelu(a.w + ad.w));
            d0 += x00; d1 += x01; d2 += x02; d3 += x03;
        }
        if (h1) {
            s1 = g_srcs[start + lane + 32];
            float4 a = g_as4[s1];
            x10 = __expf(lrelu(a.x + ad.x)); x11 = __expf(lrelu(a.y + ad.y));
            x12 = __expf(lrelu(a.z + ad.z)); x13 = __expf(lrelu(a.w + ad.w));
            d0 += x10; d1 += x11; d2 += x12; d3 += x13;
        }
        #pragma unroll
        for (int o = 16; o; o >>= 1) {
            d0 += __shfl_xor_sync(0xffffffffu, d0, o);
            d1 += __shfl_xor_sync(0xffffffffu, d1, o);
            d2 += __shfl_xor_sync(0xffffffffu, d2, o);
            d3 += __shfl_xor_sync(0xffffffffu, d3, o);
        }
        float i0 = 1.f / (d0 + 1e-16f), i1 = 1.f / (d1 + 1e-16f);
        float i2 = 1.f / (d2 + 1e-16f), i3 = 1.f / (d3 + 1e-16f);
        if (h0) {
            ssrc[w][lane] = s0;
            ealpha[w][lane] = make_float4(x00 * i0, x01 * i1, x02 * i2, x03 * i3);
        }
        if (h1) {
            ssrc[w][lane + 32] = s1;
            ealpha[w][lane + 32] = make_float4(x10 * i0, x11 * i1, x12 * i2, x13 * i3);
        }
        __syncwarp();
        #pragma unroll 4
        for (int t = 0; t < deg; t++) {
            int s = ssrc[w][t];
            float alpha = ((const float*)&ealpha[w][t])[head];
            uint2 hv = ((const uint2*)g_h16)[s * 32 + lane];
            float2 f0 = __half22float2(*reinterpret_cast<__half2*>(&hv.x));
            float2 f1 = __half22float2(*reinterpret_cast<__half2*>(&hv.y));
            acc[0] = fmaf(f0.x, alpha, acc[0]);
            acc[1] = fmaf(f0.y, alpha, acc[1]);
            acc[2] = fmaf(f1.x, alpha, acc[2]);
            acc[3] = fmaf(f1.y, alpha, acc[3]);
        }
    } else if (deg > 64) {
        float d0 = 0.f, d1 = 0.f, d2 = 0.f, d3 = 0.f;
        for (int i = lane; i < deg; i += 32) {
            int s = g_srcs[start + i];
            float4 a = g_as4[s];
            d0 += __expf(lrelu(a.x + ad.x));
            d1 += __expf(lrelu(a.y + ad.y));
            d2 += __expf(lrelu(a.z + ad.z));
            d3 += __expf(lrelu(a.w + ad.w));
        }
        #pragma unroll
        for (int o = 16; o; o >>= 1) {
            d0 += __shfl_xor_sync(0xffffffffu, d0, o);
            d1 += __shfl_xor_sync(0xffffffffu, d1, o);
            d2 += __shfl_xor_sync(0xffffffffu, d2, o);
            d3 += __shfl_xor_sync(0xffffffffu, d3, o);
        }
        float denh = (head == 0) ? d0 : (head == 1) ? d1 : (head == 2) ? d2 : d3;
        float adh  = (head == 0) ? ad.x : (head == 1) ? ad.y : (head == 2) ? ad.z : ad.w;
        float invh = 1.f / (denh + 1e-16f);
        for (int t = 0; t < deg; t++) {
            int s = g_srcs[start + t];
            float ash = ((const float*)&g_as4[s])[head];
            float alpha = __expf(lrelu(ash + adh)) * invh;
            uint2 hv = ((const uint2*)g_h16)[s * 32 + lane];
            float2 f0 = __half22float2(*reinterpret_cast<__half2*>(&hv.x));
            float2 f1 = __half22float2(*reinterpret_cast<__half2*>(&hv.y));
            acc[0] = fmaf(f0.x, alpha, acc[0]);
            acc[1] = fmaf(f0.y, alpha, acc[1]);
            acc[2] = fmaf(f1.x, alpha, acc[2]);
            acc[3] = fmaf(f1.y, alpha, acc[3]);
        }
    }

    float4 a4 = make_float4(acc[0], acc[1], acc[2], acc[3]);
    ((float4*)g_agg)[v * 32 + lane] = a4;
    bnS[w][lane] = a4;
    bnQ[w][lane] = make_float4(a4.x * a4.x, a4.y * a4.y, a4.z * a4.z, a4.w * a4.w);
    __syncthreads();
    int t = threadIdx.x;
    if (t < 128) {
        float s = 0.f;
        #pragma unroll
        for (int i = 0; i < 8; i++) s += ((const float*)&bnS[i][t >> 2])[t & 3];
        atomicAdd(&g_bnsum[bnbuf * 128 + t], s);
    } else {
        int cc = t - 128;
        float q = 0.f;
        #pragma unroll
        for (int i = 0; i < 8; i++) q += ((const float*)&bnQ[i][cc >> 2])[cc & 3];
        atomicAdd(&g_bnsq[bnbuf * 128 + cc], q);
    }
}

// ---------------- agg for layer 2 (NC=160, head-mean output) -------------------
// Lane L owns cols 4L..4L+3 (head L/10, uint2 load); lanes 0..15 own cols
// 128+2L..129+2L (all head 3, uint load). Head-mean via per-warp smem colbuf.
__global__ void __launch_bounds__(256) agg40_kernel(float* __restrict__ out) {
    __shared__ int    ssrc[8][64];
    __shared__ float4 ealpha[8][64];
    __shared__ float  colbuf[8][160];
    int w = threadIdx.x >> 5, lane = threadIdx.x & 31;
    int v = blockIdx.x * 8 + w;
    int start = g_rowptr[v];
    int deg = g_rowptr[v + 1] - start;
    float4 ad = g_ad4[v];
    const int headA = lane / 10;           // head of cols 4L..4L+3 (lane 30,31 -> 3)

    float acc[4] = {0.f, 0.f, 0.f, 0.f};
    float acc4 = 0.f, acc5 = 0.f;

    if (deg > 0 && deg <= 64) {
        int s0 = 0, s1 = 0;
        bool h0 = lane < deg, h1 = lane + 32 < deg;
        float d0 = 0.f, d1 = 0.f, d2 = 0.f, d3 = 0.f;
        float x00=0,x01=0,x02=0,x03=0, x10=0,x11=0,x12=0,x13=0;
        if (h0) {
            s0 = g_srcs[start + lane];
            float4 a = g_as4[s0];
            x00 = __expf(lrelu(a.x + ad.x)); x01 = __expf(lrelu(a.y + ad.y));
            x02 = __expf(lrelu(a.z + ad.z)); x03 = __expf(lrelu(a.w + ad.w));
            d0 += x00; d1 += x01; d2 += x02; d3 += x03;
        }
        if (h1) {
            s1 = g_srcs[start + lane + 32];
            float4 a = g_as4[s1];
            x10 = __expf(lrelu(a.x + ad.x)); x11 = __expf(lrelu(a.y + ad.y));
            x12 = __expf(lrelu(a.z + ad.z)); x13 = __expf(lrelu(a.w + ad.w));
            d0 += x10; d1 += x11; d2 += x12; d3 += x13;
        }
        #pragma unroll
        for (int o = 16; o; o >>= 1) {
            d0 += __shfl_xor_sync(0xffffffffu, d0, o);
            d1 += __shfl_xor_sync(0xffffffffu, d1, o);
            d2 += __shfl_xor_sync(0xffffffffu, d2, o);
            d3 += __shfl_xor_sync(0xffffffffu, d3, o);
        }
        float i0 = 1.f / (d0 + 1e-16f), i1 = 1.f / (d1 + 1e-16f);
        float i2 = 1.f / (d2 + 1e-16f), i3 = 1.f / (d3 + 1e-16f);
        if (h0) {
            ssrc[w][lane] = s0;
            ealpha[w][lane] = make_float4(x00 * i0, x01 * i1, x02 * i2, x03 * i3);
        }
        if (h1) {
            ssrc[w][lane + 32] = s1;
            ealpha[w][lane + 32] = make_float4(x10 * i0, x11 * i1, x12 * i2, x13 * i3);
        }
        __syncwarp();
        #pragma unroll 2
        for (int t = 0; t < deg; t++) {
            int s = ssrc[w][t];
            float4 al = ealpha[w][t];
            float alphaA = ((const float*)&al)[headA];
            uint2 hv = ((const uint2*)(g_h16 + s * 160))[lane];
            float2 f0 = __half22float2(*reinterpret_cast<__half2*>(&hv.x));
            float2 f1 = __half22float2(*reinterpret_cast<__half2*>(&hv.y));
            acc[0] = fmaf(f0.x, alphaA, acc[0]);
            acc[1] = fmaf(f0.y, alphaA, acc[1]);
            acc[2] = fmaf(f1.x, alphaA, acc[2]);
            acc[3] = fmaf(f1.y, alphaA, acc[3]);
            if (lane < 16) {
                unsigned xx = *(const unsigned*)((const char*)(g_h16 + s * 160) + 256 + lane * 4);
                float2 fe = __half22float2(*reinterpret_cast<__half2*>(&xx));
                acc4 = fmaf(fe.x, al.w, acc4);
                acc5 = fmaf(fe.y, al.w, acc5);
            }
        }
    } else if (deg > 64) {
        float d0 = 0.f, d1 = 0.f, d2 = 0.f, d3 = 0.f;
        for (int i = lane; i < deg; i += 32) {
            int s = g_srcs[start + i];
            float4 a = g_as4[s];
            d0 += __expf(lrelu(a.x + ad.x));
            d1 += __expf(lrelu(a.y + ad.y));
            d2 += __expf(lrelu(a.z + ad.z));
            d3 += __expf(lrelu(a.w + ad.w));
        }
        #pragma unroll
        for (int o = 16; o; o >>= 1) {
            d0 += __shfl_xor_sync(0xffffffffu, d0, o);
            d1 += __shfl_xor_sync(0xffffffffu, d1, o);
            d2 += __shfl_xor_sync(0xffffffffu, d2, o);
            d3 += __shfl_xor_sync(0xffffffffu, d3, o);
        }
        float inv0 = 1.f / (d0 + 1e-16f), inv1 = 1.f / (d1 + 1e-16f);
        float inv2 = 1.f / (d2 + 1e-16f), inv3 = 1.f / (d3 + 1e-16f);
        for (int t = 0; t < deg; t++) {
            int s = g_srcs[start + t];
            float4 a = g_as4[s];
            float al0 = __expf(lrelu(a.x + ad.x)) * inv0;
            float al1 = __expf(lrelu(a.y + ad.y)) * inv1;
            float al2 = __expf(lrelu(a.z + ad.z)) * inv2;
            float al3 = __expf(lrelu(a.w + ad.w)) * inv3;
            float alphaA = (headA == 0) ? al0 : (headA == 1) ? al1 : (headA == 2) ? al2 : al3;
            uint2 hv = ((const uint2*)(g_h16 + s * 160))[lane];
            float2 f0 = __half22float2(*reinterpret_cast<__half2*>(&hv.x));
            float2 f1 = __half22float2(*reinterpret_cast<__half2*>(&hv.y));
            acc[0] = fmaf(f0.x, alphaA, acc[0]);
            acc[1] = fmaf(f0.y, alphaA, acc[1]);
            acc[2] = fmaf(f1.x, alphaA, acc[2]);
            acc[3] = fmaf(f1.y, alphaA, acc[3]);
            if (lane < 16) {
                unsigned xx = *(const unsigned*)((const char*)(g_h16 + s * 160) + 256 + lane * 4);
                float2 fe = __half22float2(*reinterpret_cast<__half2*>(&xx));
                acc4 = fmaf(fe.x, al3, acc4);
                acc5 = fmaf(fe.y, al3, acc5);
            }
        }
    }

    // head-mean epilogue via per-warp column buffer
    colbuf[w][4 * lane + 0] = acc[0];
    colbuf[w][4 * lane + 1] = acc[1];
    colbuf[w][4 * lane + 2] = acc[2];
    colbuf[w][4 * lane + 3] = acc[3];
    if (lane < 16) {
        colbuf[w][128 + 2 * lane] = acc4;
        colbuf[w][129 + 2 * lane] = acc5;
    }
    __syncwarp();
    {
        int d = lane;   // d < 32
        float s = colbuf[w][d] + colbuf[w][40 + d] + colbuf[w][80 + d] + colbuf[w][120 + d];
        out[v * 40 + d] = 0.25f * s;
        if (lane < 8) {
            int d2 = 32 + lane;
            float s2 = colbuf[w][d2] + colbuf[w][40 + d2] + colbuf[w][80 + d2] + colbuf[w][120 + d2];
            out[v * 40 + d2] = 0.25f * s2;
        }
    }
}

// ---------------- launch ----------------
extern "C" void kernel_launch(void* const* d_in, const int* in_sizes, int n_in,
                              void* d_out, int out_size) {
    (void)in_sizes; (void)n_in; (void)out_size;
    const float* x     = (const float*)d_in[0];
    const int*   ei    = (const int*)d_in[1];
    const float* w01   = (const float*)d_in[2];
    const float* s01   = (const float*)d_in[3];
    const float* att01 = (const float*)d_in[4];
    const float* w2    = (const float*)d_in[5];
    const float* s2    = (const float*)d_in[6];
    const float* att2  = (const float*)d_in[7];
    const float* gamma = (const float*)d_in[8];
    const float* beta  = (const float*)d_in[9];
    float* out = (float*)d_out;
    const int* srcp = ei;
    const int* dstp = ei + NE;

    const int THR_SMEM  = (32768 + 1024 + 16 + 2048) * 4;               // ~140 KB
    const int G128_SMEM = 1024 + 2 * 128 * 72 * 2 + 2 * 136 * 72 * 2;   // ~75 KB
    const int G160_SMEM = 1024 + 2 * 128 * 72 * 2 + 2 * 168 * 72 * 2;   // ~84 KB
    cudaFuncSetAttribute(thr_kernel, cudaFuncAttributeMaxDynamicSharedMemorySize, THR_SMEM);
    cudaFuncSetAttribute(gemm_kernel<128>, cudaFuncAttributeMaxDynamicSharedMemorySize, G128_SMEM);
    cudaFuncSetAttribute(gemm_kernel<160>, cudaFuncAttributeMaxDynamicSharedMemorySize, G160_SMEM);

    const int GB = (NN + 127) / 128;   // 782
    const int AB = NN / 8;             // 12500 (warp per node)

    // Fork CSR side stream at the very start (no dependence on thr/mask).
    cudaStream_t side;
    cudaEvent_t evFork, evJoin;
    cudaStreamCreateWithFlags(&side, cudaStreamNonBlocking);
    cudaEventCreateWithFlags(&evFork, cudaEventDisableTiming);
    cudaEventCreateWithFlags(&evJoin, cudaEventDisableTiming);

    cudaEventRecord(evFork, 0);
    cudaStreamWaitEvent(side, evFork, 0);

    hist_kernel<<<(NE + 255) / 256, 256, 0, side>>>(dstp);
    scan1_kernel<<<98, 1024, 0, side>>>();
    scan2_kernel<<<1, 32, 0, side>>>();
    scan3_kernel<<<98, 1024, 0, side>>>();
    scatter_kernel<<<(NE + 255) / 256, 256, 0, side>>>(srcp, dstp);
    cudaEventRecord(evJoin, side);

    // main: threshold -> masked weights -> gemm L0
    thr_kernel<<<1, 1024, THR_SMEM>>>(s01, s2);
    maskwext_kernel<<<53, 1024>>>(w01, s01, att01, w2, s2, att2);
    gemm_kernel<128><<<GB, 512, G128_SMEM>>>(x, 0, -1, gamma, beta);

    cudaStreamWaitEvent(0, evJoin, 0);

    agg_kernel<<<AB, 256>>>(0);
    gemm_kernel<128><<<GB, 512, G128_SMEM>>>(nullptr, 1, 0, gamma, beta);
    agg_kernel<<<AB, 256>>>(1);
    gemm_kernel<160><<<GB, 512, G160_SMEM>>>(nullptr, 2, 1, gamma + 128, beta + 128);
    agg40_kernel<<<AB, 256>>>(out);

    cudaStreamDestroy(side);
    cudaEventDestroy(evFork);
    cudaEventDestroy(evJoin);
}

// round 16
// speedup vs baseline: 1.5871x; 1.0180x over previous
#include <cuda_runtime.h>
#include <cuda_bf16.h>
#include <cuda_fp16.h>
#include <math_constants.h>
#include <cstdint>

#define NN 100000
#define NE 1600000

typedef unsigned long long ull;

// ---------------- device scratch ----------------
__device__ __half g_h16[NN * 160];      // h in fp16 (gather input)
__device__ __half g_aggh[NN * 128];     // inter-layer agg output in fp16
__device__ float4 g_as4[NN];
__device__ float4 g_ad4[NN];
__device__ int    g_deg[NN];
__device__ int    g_rowptr[NN + 1];
__device__ int    g_pos[NN];
__device__ int    g_srcs[NE];
__device__ __nv_bfloat16 g_Bh[3 * 22528];
__device__ __nv_bfloat16 g_Bl[3 * 22528];
__device__ float  g_thr;
__device__ float  g_bnsum[256], g_bnsq[256];
__device__ int    g_bsum[98], g_boff[98];

__device__ __forceinline__ float lrelu(float x) { return (x >= 0.f) ? x : 0.2f * x; }

__device__ __forceinline__ uint32_t smem_u32(const void* p) {
    uint32_t a;
    asm("{ .reg .u64 t; cvta.to.shared.u64 t, %1; cvt.u32.u64 %0, t; }" : "=r"(a) : "l"(p));
    return a;
}
__device__ __forceinline__ void ldmx4(uint32_t addr, uint32_t r[4]) {
    asm volatile("ldmatrix.sync.aligned.m8n8.x4.shared.b16 {%0,%1,%2,%3}, [%4];"
        : "=r"(r[0]), "=r"(r[1]), "=r"(r[2]), "=r"(r[3]) : "r"(addr));
}
__device__ __forceinline__ void ldmx2(uint32_t addr, uint32_t r[2]) {
    asm volatile("ldmatrix.sync.aligned.m8n8.x2.shared.b16 {%0,%1}, [%2];"
        : "=r"(r[0]), "=r"(r[1]) : "r"(addr));
}
__device__ __forceinline__ void mma_bf16(float c[4], const uint32_t a[4],
                                         uint32_t b0, uint32_t b1) {
    asm volatile("mma.sync.aligned.m16n8k16.row.col.f32.bf16.bf16.f32 "
        "{%0,%1,%2,%3}, {%4,%5,%6,%7}, {%8,%9}, {%0,%1,%2,%3};"
        : "+f"(c[0]), "+f"(c[1]), "+f"(c[2]), "+f"(c[3])
        : "r"(a[0]), "r"(a[1]), "r"(a[2]), "r"(a[3]), "r"(b0), "r"(b1));
}
__device__ __forceinline__ void bfsplit(float v, __nv_bfloat16& h, __nv_bfloat16& l) {
    h = __float2bfloat16(v);
    l = __float2bfloat16(v - __bfloat162float(h));
}

// ---------------- exact percentile: 15-bit histogram select ----------------
__global__ void thr_kernel(const float* __restrict__ s01, const float* __restrict__ s2) {
    extern __shared__ unsigned sm[];
    unsigned* hist = sm;
    unsigned* tsum = sm + 32768;
    unsigned* misc = sm + 33792;
    unsigned* list = sm + 33808;
    const int t = threadIdx.x;
    const int K = 26624;

    #pragma unroll
    for (int j = 0; j < 32; j++) hist[t + j * 1024] = 0;
    if (t < 16) misc[t] = 0;
    __syncthreads();

    for (int i = t; i < 32768; i += 1024)
        atomicAdd(&hist[__float_as_uint(fabsf(s01[i])) >> 16], 1u);
    for (int i = t; i < 20480; i += 1024)
        atomicAdd(&hist[__float_as_uint(fabsf(s2[i])) >> 16], 1u);
    __syncthreads();

    unsigned s = 0;
    #pragma unroll
    for (int j = 0; j < 32; j++) s += hist[t * 32 + j];
    tsum[t] = s;
    __syncthreads();
    for (int off = 1; off < 1024; off <<= 1) {
        unsigned x = (t >= off) ? tsum[t - off] : 0u;
        __syncthreads();
        tsum[t] += x;
        __syncthreads();
    }
    {
        unsigned excl = (t == 0) ? 0u : tsum[t - 1];
        if ((unsigned)K >= excl && (unsigned)K < tsum[t]) {
            unsigned run = excl;
            #pragma unroll
            for (int j = 0; j < 32; j++) {
                unsigned c = hist[t * 32 + j];
                if ((unsigned)K < run + c) { misc[0] = (unsigned)(t * 32 + j); misc[1] = (unsigned)K - run; break; }
                run += c;
            }
        }
    }
    __syncthreads();
    const unsigned bin = misc[0], r = misc[1];

    for (int i = t; i < 32768; i += 1024) {
        unsigned u = __float_as_uint(fabsf(s01[i]));
        if ((u >> 16) == bin) {
            unsigned idx = atomicAdd(&misc[2], 1u);
            if (idx < 2048) list[idx] = u;
        }
    }
    for (int i = t; i < 20480; i += 1024) {
        unsigned u = __float_as_uint(fabsf(s2[i]));
        if ((u >> 16) == bin) {
            unsigned idx = atomicAdd(&misc[2], 1u);
            if (idx < 2048) list[idx] = u;
        }
    }
    __syncthreads();
    const int cnt = (int)min(misc[2], 2048u);
    for (int i = t; i < cnt; i += 1024) {
        unsigned v = list[i];
        int rank = 0;
        for (int j = 0; j < cnt; j++) {
            unsigned u = list[j];
            rank += (u < v) || (u == v && j < i);
        }
        if (rank == (int)r) g_thr = __uint_as_float(v);
    }
}

// ---------------- masked weights + attention-folded columns (merged) ----------
__global__ void __launch_bounds__(1024) maskwext_kernel(
        const float* __restrict__ w01, const float* __restrict__ s01,
        const float* __restrict__ att01,
        const float* __restrict__ w2, const float* __restrict__ s2,
        const float* __restrict__ att2) {
    float thr = g_thr;
    int b = blockIdx.x, t = threadIdx.x;
    if (b < 52) {
        int i = b * 1024 + t;
        if (i < 53248) {
            int L, k, n;
            float val;
            if (i < 16384) {
                L = 0; k = i >> 7; n = i & 127;
                val = (fabsf(s01[i]) < thr) ? 0.f : w01[i];
            } else if (i < 32768) {
                int j = i - 16384;
                L = 1; k = j >> 7; n = j & 127;
                val = (fabsf(s01[i]) < thr) ? 0.f : w01[i];
            } else {
                int j = i - 32768;
                L = 2; k = j / 160; n = j - k * 160;
                val = (fabsf(s2[j]) < thr) ? 0.f : w2[j];
            }
            __nv_bfloat16 hi, lo;
            bfsplit(val, hi, lo);
            int idx = L * 22528 + n * 128 + k;
            g_Bh[idx] = hi;
            g_Bl[idx] = lo;
        }
    } else {
        int k = t >> 3, slot = t & 7, sd = slot >> 2, h = slot & 3;
        #pragma unroll
        for (int L = 0; L < 2; L++) {
            float acc = 0.f;
            for (int d = 0; d < 32; d++) {
                int idx = L * 16384 + k * 128 + h * 32 + d;
                float w = (fabsf(s01[idx]) < thr) ? 0.f : w01[idx];
                acc = fmaf(w, att01[L * 256 + sd * 128 + h * 32 + d], acc);
            }
            __nv_bfloat16 hi, lo;
            bfsplit(acc, hi, lo);
            int idx2 = L * 22528 + (128 + slot) * 128 + k;
            g_Bh[idx2] = hi; g_Bl[idx2] = lo;
        }
        {
            float acc = 0.f;
            for (int d = 0; d < 40; d++) {
                int idx = k * 160 + h * 40 + d;
                float w = (fabsf(s2[idx]) < thr) ? 0.f : w2[idx];
                acc = fmaf(w, att2[sd * 160 + h * 40 + d], acc);
            }
            __nv_bfloat16 hi, lo;
            bfsplit(acc, hi, lo);
            int idx2 = 2 * 22528 + (160 + slot) * 128 + k;
            g_Bh[idx2] = hi; g_Bl[idx2] = lo;
        }
    }
}

// ---------------- CSR build ----------------
__global__ void hist_kernel(const int* __restrict__ dst) {
    int e = blockIdx.x * blockDim.x + threadIdx.x;
    if (e < NE) atomicAdd(&g_deg[dst[e]], 1);
}
__global__ void scan1_kernel() {
    __shared__ int red[32];
    int t = threadIdx.x, b = blockIdx.x;
    int i = b * 1024 + t;
    int s = (i < NN) ? g_deg[i] : 0;
    #pragma unroll
    for (int o = 16; o; o >>= 1) s += __shfl_xor_sync(0xffffffffu, s, o);
    if ((t & 31) == 0) red[t >> 5] = s;
    __syncthreads();
    if (t < 32) {
        int x = red[t];
        #pragma unroll
        for (int o = 16; o; o >>= 1) x += __shfl_xor_sync(0xffffffffu, x, o);
        if (t == 0) g_bsum[b] = x;
    }
}
__global__ void scan2_kernel() {
    if (threadIdx.x == 0) {
        int run = 0;
        for (int b = 0; b < 98; b++) { g_boff[b] = run; run += g_bsum[b]; }
        g_rowptr[NN] = run;
    }
}
__global__ void scan3_kernel() {
    __shared__ int sm[1024];
    int t = threadIdx.x, b = blockIdx.x;
    int i = b * 1024 + t;
    int v = (i < NN) ? g_deg[i] : 0;
    sm[t] = v;
    __syncthreads();
    for (int off = 1; off < 1024; off <<= 1) {
        int x = (t >= off) ? sm[t - off] : 0;
        __syncthreads();
        sm[t] += x;
        __syncthreads();
    }
    if (i < NN) {
        int excl = sm[t] - v + g_boff[b];
        g_rowptr[i] = excl;
        g_pos[i] = excl;
        g_deg[i] = 0;
    }
}
__global__ void scatter_kernel(const int* __restrict__ src, const int* __restrict__ dst) {
    int e = blockIdx.x * blockDim.x + threadIdx.x;
    if (blockIdx.x == 0 && threadIdx.x < 256) {
        g_bnsum[threadIdx.x] = 0.f;
        g_bnsq[threadIdx.x] = 0.f;
    }
    if (e < NE) {
        int d = dst[e];
        int p = atomicAdd(&g_pos[d], 1);
        g_srcs[p] = src[e];
    }
}

// ---------------- mma.sync bf16 GEMM, A K-chunked; B full-resident if NC=128 ---
template<int NC, bool XH>
__global__ void __launch_bounds__(512, 2) gemm_kernel(const float* __restrict__ Xopt,
                                                      int widx, int bnbuf,
                                                      const float* __restrict__ gamma,
                                                      const float* __restrict__ beta) {
    constexpr int NCP = NC + 8;
    constexpr int NT = NCP / 8;
    constexpr int NPAIRS = (NT + 1) / 2;
    constexpr int MAXP = (NPAIRS + 1) / 2;
    constexpr int KS = 72;                     // A chunk row stride (halfs)
    constexpr bool BFULL = (NC == 128);
    constexpr int BKS = BFULL ? 136 : 72;      // B row stride (halfs)
    extern __shared__ char dsm[];
    float* SC = (float*)dsm;
    float* SH = SC + 128;
    __nv_bfloat16* Ah = (__nv_bfloat16*)(dsm + 1024);
    __nv_bfloat16* Al = Ah + 128 * KS;
    __nv_bfloat16* Bh = Al + 128 * KS;
    __nv_bfloat16* Bl = Bh + NCP * BKS;

    const int useBN = (bnbuf >= 0);
    const int tid = threadIdx.x;
    const int wid = tid >> 5, lane = tid & 31;
    const int wy = wid & 7;
    const int wn = wid >> 3;
    const int row0 = blockIdx.x * 128;

    if (useBN && tid < 128) {
        float mu = g_bnsum[bnbuf * 128 + tid] * (1.f / NN);
        float var = g_bnsq[bnbuf * 128 + tid] * (1.f / NN) - mu * mu;
        float sc = rsqrtf(var + 1e-5f) * gamma[tid];
        SC[tid] = sc;
        SH[tid] = fmaf(-mu, sc, beta[tid]);
    }
    if (useBN) __syncthreads();

    float c[MAXP][2][4];
    #pragma unroll
    for (int pi = 0; pi < MAXP; pi++)
        #pragma unroll
        for (int u = 0; u < 2; u++)
            #pragma unroll
            for (int q = 0; q < 4; q++) c[pi][u][q] = 0.f;

    const uint32_t au = smem_u32(Ah), alu = smem_u32(Al);
    const uint32_t bu = smem_u32(Bh), blu = smem_u32(Bl);
    const int arow = wy * 16 + (lane & 15);
    const int acol0 = (lane >> 4) * 8;
    const int brow_x4 = (lane & 7) + ((lane >> 4) * 8);
    const int bcolsel = ((lane >> 3) & 1) * 8;

    for (int kc = 0; kc < 2; kc++) {
        // B copy: full once (NC=128) or per-chunk (NC=160)
        if (!BFULL || kc == 0) {
            if (BFULL) {
                const char* sH = (const char*)(g_Bh + widx * 22528);
                const char* sL = (const char*)(g_Bl + widx * 22528);
                for (int i = tid; i < NCP * 16; i += 512) {
                    int row = i >> 4, seg = i & 15;
                    *(float4*)((char*)Bh + row * (BKS * 2) + seg * 16) = *(const float4*)(sH + row * 256 + seg * 16);
                    *(float4*)((char*)Bl + row * (BKS * 2) + seg * 16) = *(const float4*)(sL + row * 256 + seg * 16);
                }
            } else {
                const char* sH = (const char*)(g_Bh + widx * 22528) + kc * 128;
                const char* sL = (const char*)(g_Bl + widx * 22528) + kc * 128;
                for (int i = tid; i < NCP * 8; i += 512) {
                    int row = i >> 3, seg = i & 7;
                    *(float4*)((char*)Bh + row * (BKS * 2) + seg * 16) = *(const float4*)(sH + row * 256 + seg * 16);
                    *(float4*)((char*)Bl + row * (BKS * 2) + seg * 16) = *(const float4*)(sL + row * 256 + seg * 16);
                }
            }
        }
        // A chunk: load X cols [kc*64, +64), BN+ReLU, bf16 hi/lo split
        {
            __nv_bfloat162* A2h = (__nv_bfloat162*)Ah;
            __nv_bfloat162* A2l = (__nv_bfloat162*)Al;
            for (int i = tid; i < 2048; i += 512) {
                int r = i >> 4, c4l = i & 15;
                int c4 = kc * 16 + c4l;
                int gr = row0 + r;
                float4 v = make_float4(0.f, 0.f, 0.f, 0.f);
                if (gr < NN) {
                    if (XH) {
                        uint2 pk = *(const uint2*)(g_aggh + gr * 128 + c4 * 4);
                        float2 f0 = __half22float2(*reinterpret_cast<__half2*>(&pk.x));
                        float2 f1 = __half22float2(*reinterpret_cast<__half2*>(&pk.y));
                        v = make_float4(f0.x, f0.y, f1.x, f1.y);
                    } else {
                        v = ((const float4*)Xopt)[gr * 32 + c4];
                    }
                    if (useBN) {
                        float4 sc = ((const float4*)SC)[c4];
                        float4 sh = ((const float4*)SH)[c4];
                        v.x = fmaxf(fmaf(v.x, sc.x, sh.x), 0.f);
                        v.y = fmaxf(fmaf(v.y, sc.y, sh.y), 0.f);
                        v.z = fmaxf(fmaf(v.z, sc.z, sh.z), 0.f);
                        v.w = fmaxf(fmaf(v.w, sc.w, sh.w), 0.f);
                    }
                }
                __nv_bfloat16 hx, lx, hy, ly, hz, lz, hw, lw;
                bfsplit(v.x, hx, lx); bfsplit(v.y, hy, ly);
                bfsplit(v.z, hz, lz); bfsplit(v.w, hw, lw);
                int o2 = r * (KS / 2) + c4l * 2;
                __nv_bfloat162 p0, p1, q0, q1;
                p0.x = hx; p0.y = hy; p1.x = hz; p1.y = hw;
                q0.x = lx; q0.y = ly; q1.x = lz; q1.y = lw;
                A2h[o2] = p0; A2h[o2 + 1] = p1;
                A2l[o2] = q0; A2l[o2 + 1] = q1;
            }
        }
        __syncthreads();

        const int bkbase = BFULL ? kc * 64 : 0;
        for (int kb = 0; kb < 4; kb++) {
            uint32_t ah[4], al[4];
            uint32_t aoff = (uint32_t)((arow * KS + kb * 16 + acol0) * 2);
            ldmx4(au + aoff, ah);
            ldmx4(alu + aoff, al);
            #pragma unroll
            for (int pi = 0; pi < MAXP; pi++) {
                int p = wn + 2 * pi;
                if (p >= NPAIRS) break;
                if (2 * p + 1 < NT) {
                    uint32_t bh[4], bl[4];
                    uint32_t boff = (uint32_t)(((p * 16 + brow_x4) * BKS + bkbase + kb * 16 + bcolsel) * 2);
                    ldmx4(bu + boff, bh);
                    ldmx4(blu + boff, bl);
                    mma_bf16(c[pi][0], ah, bh[0], bh[1]);
                    mma_bf16(c[pi][0], ah, bl[0], bl[1]);
                    mma_bf16(c[pi][0], al, bh[0], bh[1]);
                    mma_bf16(c[pi][1], ah, bh[2], bh[3]);
                    mma_bf16(c[pi][1], ah, bl[2], bl[3]);
                    mma_bf16(c[pi][1], al, bh[2], bh[3]);
                } else {
                    uint32_t bh[2], bl[2];
                    int brow2 = 2 * p * 8 + (lane & 7);
                    uint32_t boff = (uint32_t)((brow2 * BKS + bkbase + kb * 16 + bcolsel) * 2);
                    ldmx2(bu + boff, bh);
                    ldmx2(blu + boff, bl);
                    mma_bf16(c[pi][0], ah, bh[0], bh[1]);
                    mma_bf16(c[pi][0], ah, bl[0], bl[1]);
                    mma_bf16(c[pi][0], al, bh[0], bh[1]);
                }
            }
        }
        __syncthreads();
    }

    const int g = lane >> 2, tig = lane & 3;
    const int rA = row0 + wy * 16 + g;
    const int rB = rA + 8;
    const bool okA = rA < NN, okB = rB < NN;
    #pragma unroll
    for (int pi = 0; pi < MAXP; pi++) {
        int p = wn + 2 * pi;
        if (p >= NPAIRS) break;
        #pragma unroll
        for (int u = 0; u < 2; u++) {
            int ntI = 2 * p + u;
            if (ntI >= NT) break;
            if (ntI < NT - 1) {
                if (okA) *(__half2*)&g_h16[rA * NC + ntI * 8 + tig * 2] =
                    __floats2half2_rn(c[pi][u][0], c[pi][u][1]);
                if (okB) *(__half2*)&g_h16[rB * NC + ntI * 8 + tig * 2] =
                    __floats2half2_rn(c[pi][u][2], c[pi][u][3]);
            } else {
                float e0 = c[pi][u][0], e1 = c[pi][u][1], e2 = c[pi][u][2], e3 = c[pi][u][3];
                float o0 = __shfl_xor_sync(0xffffffffu, e0, 1);
                float o1 = __shfl_xor_sync(0xffffffffu, e1, 1);
                float o2 = __shfl_xor_sync(0xffffffffu, e2, 1);
                float o3 = __shfl_xor_sync(0xffffffffu, e3, 1);
                if (tig == 0) {
                    if (okA) g_as4[rA] = make_float4(e0, e1, o0, o1);
                    if (okB) g_as4[rB] = make_float4(e2, e3, o2, o3);
                } else if (tig == 2) {
                    if (okA) g_ad4[rA] = make_float4(e0, e1, o0, o1);
                    if (okB) g_ad4[rB] = make_float4(e2, e3, o2, o3);
                }
            }
        }
    }
}

// ---------------- agg for layers 0/1 (NC=128, warp/node, fp16 in/out) ----------
__global__ void __launch_bounds__(256) agg_kernel(int bnbuf) {
    __shared__ int    ssrc[8][64];
    __shared__ float4 ealpha[8][64];
    __shared__ float4 bnS[8][32];
    __shared__ float4 bnQ[8][32];
    int w = threadIdx.x >> 5, lane = threadIdx.x & 31;
    int v = blockIdx.x * 8 + w;
    int head = lane >> 3;
    int start = g_rowptr[v];
    int deg = g_rowptr[v + 1] - start;
    float4 ad = g_ad4[v];

    float acc[4] = {0.f, 0.f, 0.f, 0.f};

    if (deg > 0 && deg <= 64) {
        int s0 = 0, s1 = 0;
        bool h0 = lane < deg, h1 = lane + 32 < deg;
        float d0 = 0.f, d1 = 0.f, d2 = 0.f, d3 = 0.f;
        float x00=0,x01=0,x02=0,x03=0, x10=0,x11=0,x12=0,x13=0;
        if (h0) {
            s0 = g_srcs[start + lane];
            float4 a = g_as4[s0];
            x00 = __expf(lrelu(a.x + ad.x)); x01 = __expf(lrelu(a.y + ad.y));
            x02 = __expf(lrelu(a.z + ad.z)); x03 = __expf(lrelu(a.w + ad.w));
            d0 += x00; d1 += x01; d2 += x02; d3 += x03;
        }
        if (h1) {
            s1 = g_srcs[start + lane + 32];
            float4 a = g_as4[s1];
            x10 = __expf(lrelu(a.x + ad.x)); x11 = __expf(lrelu(a.y + ad.y));
            x12 = __expf(lrelu(a.z + ad.z)); x13 = __expf(lrelu(a.w + ad.w));
            d0 += x10; d1 += x11; d2 += x12; d3 += x13;
        }
        #pragma unroll
        for (int o = 16; o; o >>= 1) {
            d0 += __shfl_xor_sync(0xffffffffu, d0, o);
            d1 += __shfl_xor_sync(0xffffffffu, d1, o);
            d2 += __shfl_xor_sync(0xffffffffu, d2, o);
            d3 += __shfl_xor_sync(0xffffffffu, d3, o);
        }
        float i0 = 1.f / (d0 + 1e-16f), i1 = 1.f / (d1 + 1e-16f);
        float i2 = 1.f / (d2 + 1e-16f), i3 = 1.f / (d3 + 1e-16f);
        if (h0) {
            ssrc[w][lane] = s0;
            ealpha[w][lane] = make_float4(x00 * i0, x01 * i1, x02 * i2, x03 * i3);
        }
        if (h1) {
            ssrc[w][lane + 32] = s1;
            ealpha[w][lane + 32] = make_float4(x10 * i0, x11 * i1, x12 * i2, x13 * i3);
        }
        __syncwarp();
        #pragma unroll 4
        for (int t = 0; t < deg; t++) {
            int s = ssrc[w][t];
            float alpha = ((const float*)&ealpha[w][t])[head];
            uint2 hv = ((const uint2*)g_h16)[s * 32 + lane];
            float2 f0 = __half22float2(*reinterpret_cast<__half2*>(&hv.x));
            float2 f1 = __half22float2(*reinterpret_cast<__half2*>(&hv.y));
            acc[0] = fmaf(f0.x, alpha, acc[0]);
            acc[1] = fmaf(f0.y, alpha, acc[1]);
            acc[2] = fmaf(f1.x, alpha, acc[2]);
            acc[3] = fmaf(f1.y, alpha, acc[3]);
        }
    } else if (deg > 64) {
        float d0 = 0.f, d1 = 0.f, d2 = 0.f, d3 = 0.f;
        for (int i = lane; i < deg; i += 32) {
            int s = g_srcs[start + i];
            float4 a = g_as4[s];
            d0 += __expf(lrelu(a.x + ad.x));
            d1 += __expf(lrelu(a.y + ad.y));
            d2 += __expf(lrelu(a.z + ad.z));
            d3 += __expf(lrelu(a.w + ad.w));
        }
        #pragma unroll
        for (int o = 16; o; o >>= 1) {
            d0 += __shfl_xor_sync(0xffffffffu, d0, o);
            d1 += __shfl_xor_sync(0xffffffffu, d1, o);
            d2 += __shfl_xor_sync(0xffffffffu, d2, o);
            d3 += __shfl_xor_sync(0xffffffffu, d3, o);
        }
        float denh = (head == 0) ? d0 : (head == 1) ? d1 : (head == 2) ? d2 : d3;
        float adh  = (head == 0) ? ad.x : (head == 1) ? ad.y : (head == 2) ? ad.z : ad.w;
        float invh = 1.f / (denh + 1e-16f);
        for (int t = 0; t < deg; t++) {
            int s = g_srcs[start + t];
            float ash = ((const float*)&g_as4[s])[head];
            float alpha = __expf(lrelu(ash + adh)) * invh;
            uint2 hv = ((const uint2*)g_h16)[s * 32 + lane];
            float2 f0 = __half22float2(*reinterpret_cast<__half2*>(&hv.x));
            float2 f1 = __half22float2(*reinterpret_cast<__half2*>(&hv.y));
            acc[0] = fmaf(f0.x, alpha, acc[0]);
            acc[1] = fmaf(f0.y, alpha, acc[1]);
            acc[2] = fmaf(f1.x, alpha, acc[2]);
            acc[3] = fmaf(f1.y, alpha, acc[3]);
        }
    }

    // store fp16 agg; BN sums in fp32 from pre-conversion values
    uint2 pk;
    *reinterpret_cast<__half2*>(&pk.x) = __floats2half2_rn(acc[0], acc[1]);
    *reinterpret_cast<__half2*>(&pk.y) = __floats2half2_rn(acc[2], acc[3]);
    ((uint2*)g_aggh)[v * 32 + lane] = pk;
    bnS[w][lane] = make_float4(acc[0], acc[1], acc[2], acc[3]);
    bnQ[w][lane] = make_float4(acc[0] * acc[0], acc[1] * acc[1],
                               acc[2] * acc[2], acc[3] * acc[3]);
    __syncthreads();
    int t = threadIdx.x;
    if (t < 128) {
        float s = 0.f;
        #pragma unroll
        for (int i = 0; i < 8; i++) s += ((const float*)&bnS[i][t >> 2])[t & 3];
        atomicAdd(&g_bnsum[bnbuf * 128 + t], s);
    } else {
        int cc = t - 128;
        float q = 0.f;
        #pragma unroll
        for (int i = 0; i < 8; i++) q += ((const float*)&bnQ[i][cc >> 2])[cc & 3];
        atomicAdd(&g_bnsq[bnbuf * 128 + cc], q);
    }
}

// ---------------- agg for layer 2 (NC=160, head-mean output) -------------------
__global__ void __launch_bounds__(256) agg40_kernel(float* __restrict__ out) {
    __shared__ int    ssrc[8][64];
    __shared__ float4 ealpha[8][64];
    __shared__ float  colbuf[8][160];
    int w = threadIdx.x >> 5, lane = threadIdx.x & 31;
    int v = blockIdx.x * 8 + w;
    int start = g_rowptr[v];
    int deg = g_rowptr[v + 1] - start;
    float4 ad = g_ad4[v];
    const int headA = lane / 10;

    float acc[4] = {0.f, 0.f, 0.f, 0.f};
    float acc4 = 0.f, acc5 = 0.f;

    if (deg > 0 && deg <= 64) {
        int s0 = 0, s1 = 0;
        bool h0 = lane < deg, h1 = lane + 32 < deg;
        float d0 = 0.f, d1 = 0.f, d2 = 0.f, d3 = 0.f;
        float x00=0,x01=0,x02=0,x03=0, x10=0,x11=0,x12=0,x13=0;
        if (h0) {
            s0 = g_srcs[start + lane];
            float4 a = g_as4[s0];
            x00 = __expf(lrelu(a.x + ad.x)); x01 = __expf(lrelu(a.y + ad.y));
            x02 = __expf(lrelu(a.z + ad.z)); x03 = __expf(lrelu(a.w + ad.w));
            d0 += x00; d1 += x01; d2 += x02; d3 += x03;
        }
        if (h1) {
            s1 = g_srcs[start + lane + 32];
            float4 a = g_as4[s1];
            x10 = __expf(lrelu(a.x + ad.x)); x11 = __expf(lrelu(a.y + ad.y));
            x12 = __expf(lrelu(a.z + ad.z)); x13 = __expf(lrelu(a.w + ad.w));
            d0 += x10; d1 += x11; d2 += x12; d3 += x13;
        }
        #pragma unroll
        for (int o = 16; o; o >>= 1) {
            d0 += __shfl_xor_sync(0xffffffffu, d0, o);
            d1 += __shfl_xor_sync(0xffffffffu, d1, o);
            d2 += __shfl_xor_sync(0xffffffffu, d2, o);
            d3 += __shfl_xor_sync(0xffffffffu, d3, o);
        }
        float i0 = 1.f / (d0 + 1e-16f), i1 = 1.f / (d1 + 1e-16f);
        float i2 = 1.f / (d2 + 1e-16f), i3 = 1.f / (d3 + 1e-16f);
        if (h0) {
            ssrc[w][lane] = s0;
            ealpha[w][lane] = make_float4(x00 * i0, x01 * i1, x02 * i2, x03 * i3);
        }
        if (h1) {
            ssrc[w][lane + 32] = s1;
            ealpha[w][lane + 32] = make_float4(x10 * i0, x11 * i1, x12 * i2, x13 * i3);
        }
        __syncwarp();
        #pragma unroll 2
        for (int t = 0; t < deg; t++) {
            int s = ssrc[w][t];
            float4 al = ealpha[w][t];
            float alphaA = ((const float*)&al)[headA];
            uint2 hv = ((const uint2*)(g_h16 + s * 160))[lane];
            float2 f0 = __half22float2(*reinterpret_cast<__half2*>(&hv.x));
            float2 f1 = __half22float2(*reinterpret_cast<__half2*>(&hv.y));
            acc[0] = fmaf(f0.x, alphaA, acc[0]);
            acc[1] = fmaf(f0.y, alphaA, acc[1]);
            acc[2] = fmaf(f1.x, alphaA, acc[2]);
            acc[3] = fmaf(f1.y, alphaA, acc[3]);
            if (lane < 16) {
                unsigned xx = *(const unsigned*)((const char*)(g_h16 + s * 160) + 256 + lane * 4);
                float2 fe = __half22float2(*reinterpret_cast<__half2*>(&xx));
                acc4 = fmaf(fe.x, al.w, acc4);
                acc5 = fmaf(fe.y, al.w, acc5);
            }
        }
    } else if (deg > 64) {
        float d0 = 0.f, d1 = 0.f, d2 = 0.f, d3 = 0.f;
        for (int i = lane; i < deg; i += 32) {
            int s = g_srcs[start + i];
            float4 a = g_as4[s];
            d0 += __expf(lrelu(a.x + ad.x));
            d1 += __expf(lrelu(a.y + ad.y));
            d2 += __expf(lrelu(a.z + ad.z));
            d3 += __expf(lrelu(a.w + ad.w));
        }
        #pragma unroll
        for (int o = 16; o; o >>= 1) {
            d0 += __shfl_xor_sync(0xffffffffu, d0, o);
            d1 += __shfl_xor_sync(0xffffffffu, d1, o);
            d2 += __shfl_xor_sync(0xffffffffu, d2, o);
            d3 += __shfl_xor_sync(0xffffffffu, d3, o);
        }
        float inv0 = 1.f / (d0 + 1e-16f), inv1 = 1.f / (d1 + 1e-16f);
        float inv2 = 1.f / (d2 + 1e-16f), inv3 = 1.f / (d3 + 1e-16f);
        for (int t = 0; t < deg; t++) {
            int s = g_srcs[start + t];
            float4 a = g_as4[s];
            float al0 = __expf(lrelu(a.x + ad.x)) * inv0;
            float al1 = __expf(lrelu(a.y + ad.y)) * inv1;
            float al2 = __expf(lrelu(a.z + ad.z)) * inv2;
            float al3 = __expf(lrelu(a.w + ad.w)) * inv3;
            float alphaA = (headA == 0) ? al0 : (headA == 1) ? al1 : (headA == 2) ? al2 : al3;
            uint2 hv = ((const uint2*)(g_h16 + s * 160))[lane];
            float2 f0 = __half22float2(*reinterpret_cast<__half2*>(&hv.x));
            float2 f1 = __half22float2(*reinterpret_cast<__half2*>(&hv.y));
            acc[0] = fmaf(f0.x, alphaA, acc[0]);
            acc[1] = fmaf(f0.y, alphaA, acc[1]);
            acc[2] = fmaf(f1.x, alphaA, acc[2]);
            acc[3] = fmaf(f1.y, alphaA, acc[3]);
            if (lane < 16) {
                unsigned xx = *(const unsigned*)((const char*)(g_h16 + s * 160) + 256 + lane * 4);
                float2 fe = __half22float2(*reinterpret_cast<__half2*>(&xx));
                acc4 = fmaf(fe.x, al3, acc4);
                acc5 = fmaf(fe.y, al3, acc5);
            }
        }
    }

    colbuf[w][4 * lane + 0] = acc[0];
    colbuf[w][4 * lane + 1] = acc[1];
    colbuf[w][4 * lane + 2] = acc[2];
    colbuf[w][4 * lane + 3] = acc[3];
    if (lane < 16) {
        colbuf[w][128 + 2 * lane] = acc4;
        colbuf[w][129 + 2 * lane] = acc5;
    }
    __syncwarp();
    {
        int d = lane;
        float s = colbuf[w][d] + colbuf[w][40 + d] + colbuf[w][80 + d] + colbuf[w][120 + d];
        out[v * 40 + d] = 0.25f * s;
        if (lane < 8) {
            int d2 = 32 + lane;
            float s2 = colbuf[w][d2] + colbuf[w][40 + d2] + colbuf[w][80 + d2] + colbuf[w][120 + d2];
            out[v * 40 + d2] = 0.25f * s2;
        }
    }
}

// ---------------- launch ----------------
extern "C" void kernel_launch(void* const* d_in, const int* in_sizes, int n_in,
                              void* d_out, int out_size) {
    (void)in_sizes; (void)n_in; (void)out_size;
    const float* x     = (const float*)d_in[0];
    const int*   ei    = (const int*)d_in[1];
    const float* w01   = (const float*)d_in[2];
    const float* s01   = (const float*)d_in[3];
    const float* att01 = (const float*)d_in[4];
    const float* w2    = (const float*)d_in[5];
    const float* s2    = (const float*)d_in[6];
    const float* att2  = (const float*)d_in[7];
    const float* gamma = (const float*)d_in[8];
    const float* beta  = (const float*)d_in[9];
    float* out = (float*)d_out;
    const int* srcp = ei;
    const int* dstp = ei + NE;

    const int THR_SMEM  = (32768 + 1024 + 16 + 2048) * 4;
    const int G128_SMEM = 1024 + 2 * 128 * 72 * 2 + 2 * 136 * 136 * 2;   // ~110 KB (B full)
    const int G160_SMEM = 1024 + 2 * 128 * 72 * 2 + 2 * 168 * 72 * 2;    // ~84 KB (B chunked)
    cudaFuncSetAttribute(thr_kernel, cudaFuncAttributeMaxDynamicSharedMemorySize, THR_SMEM);
    cudaFuncSetAttribute((gemm_kernel<128, false>), cudaFuncAttributeMaxDynamicSharedMemorySize, G128_SMEM);
    cudaFuncSetAttribute((gemm_kernel<128, true>), cudaFuncAttributeMaxDynamicSharedMemorySize, G128_SMEM);
    cudaFuncSetAttribute((gemm_kernel<160, true>), cudaFuncAttributeMaxDynamicSharedMemorySize, G160_SMEM);

    const int GB = (NN + 127) / 128;   // 782
    const int AB = NN / 8;             // 12500

    cudaStream_t side;
    cudaEvent_t evFork, evJoin;
    cudaStreamCreateWithFlags(&side, cudaStreamNonBlocking);
    cudaEventCreateWithFlags(&evFork, cudaEventDisableTiming);
    cudaEventCreateWithFlags(&evJoin, cudaEventDisableTiming);

    cudaEventRecord(evFork, 0);
    cudaStreamWaitEvent(side, evFork, 0);

    hist_kernel<<<(NE + 255) / 256, 256, 0, side>>>(dstp);
    scan1_kernel<<<98, 1024, 0, side>>>();
    scan2_kernel<<<1, 32, 0, side>>>();
    scan3_kernel<<<98, 1024, 0, side>>>();
    scatter_kernel<<<(NE + 255) / 256, 256, 0, side>>>(srcp, dstp);
    cudaEventRecord(evJoin, side);

    thr_kernel<<<1, 1024, THR_SMEM>>>(s01, s2);
    maskwext_kernel<<<53, 1024>>>(w01, s01, att01, w2, s2, att2);
    gemm_kernel<128, false><<<GB, 512, G128_SMEM>>>(x, 0, -1, gamma, beta);

    cudaStreamWaitEvent(0, evJoin, 0);

    agg_kernel<<<AB, 256>>>(0);
    gemm_kernel<128, true><<<GB, 512, G128_SMEM>>>(nullptr, 1, 0, gamma, beta);
    agg_kernel<<<AB, 256>>>(1);
    gemm_kernel<160, true><<<GB, 512, G160_SMEM>>>(nullptr, 2, 1, gamma + 128, beta + 128);
    agg40_kernel<<<AB, 256>>>(out);

    cudaStreamDestroy(side);
    cudaEventDestroy(evFork);
    cudaEventDestroy(evJoin);
}